// round 1
// baseline (speedup 1.0000x reference)
#include <cuda_runtime.h>
#include <math.h>

// Problem constants
#define BATCH   2
#define SEQ     2048
#define HID     2048
#define NHEADS  16
#define HDIM    128
#define MROWS   (BATCH*SEQ)        // 4096
#define EPSV    1e-6f

// ---------------------------------------------------------------------------
// Scratch (no cudaMalloc allowed -> __device__ globals)
// ---------------------------------------------------------------------------
__device__ float g_xn [MROWS*HID];
__device__ float g_q  [MROWS*HID];
__device__ float g_k  [MROWS*HID];
__device__ float g_v  [MROWS*HID];
__device__ float g_ctx[MROWS*HID];
__device__ float g_h  [MROWS*HID];
__device__ float g_y  [MROWS*HID];
__device__ float g_g1 [MROWS*HID];
__device__ float g_g3 [MROWS*HID];
__device__ float g_cos[SEQ*64];
__device__ float g_sin[SEQ*64];

// ---------------------------------------------------------------------------
// RoPE cos/sin table (double precision, computed on device each launch)
// ---------------------------------------------------------------------------
__global__ void rope_table_kernel() {
    int idx = blockIdx.x * 256 + threadIdx.x;
    if (idx < SEQ * 64) {
        int s = idx >> 6, i = idx & 63;
        double inv = pow(10000.0, -((double)(2 * i)) / 128.0);
        double ang = (double)s * inv;
        g_cos[idx] = (float)cos(ang);
        g_sin[idx] = (float)sin(ang);
    }
}

// ---------------------------------------------------------------------------
// RMSNorm: one block per row (2048 cols), 256 threads
// ---------------------------------------------------------------------------
__global__ __launch_bounds__(256) void rmsnorm_kernel(
    const float* __restrict__ x, const float* __restrict__ w, float* __restrict__ out)
{
    int row = blockIdx.x;
    const float4* xr = (const float4*)(x + (size_t)row * HID);
    float4 v0 = xr[threadIdx.x];
    float4 v1 = xr[threadIdx.x + 256];
    float ss = v0.x*v0.x + v0.y*v0.y + v0.z*v0.z + v0.w*v0.w
             + v1.x*v1.x + v1.y*v1.y + v1.z*v1.z + v1.w*v1.w;
    #pragma unroll
    for (int m = 16; m; m >>= 1) ss += __shfl_xor_sync(0xffffffffu, ss, m);
    __shared__ float red[8];
    if ((threadIdx.x & 31) == 0) red[threadIdx.x >> 5] = ss;
    __syncthreads();
    float tot = red[0] + red[1] + red[2] + red[3] + red[4] + red[5] + red[6] + red[7];
    float sc = rsqrtf(tot * (1.0f / (float)HID) + EPSV);
    const float4* wv = (const float4*)w;
    float4 w0 = wv[threadIdx.x];
    float4 w1v = wv[threadIdx.x + 256];
    float4 o0 = make_float4(v0.x*sc*w0.x,  v0.y*sc*w0.y,  v0.z*sc*w0.z,  v0.w*sc*w0.w);
    float4 o1 = make_float4(v1.x*sc*w1v.x, v1.y*sc*w1v.y, v1.z*sc*w1v.z, v1.w*sc*w1v.w);
    float4* orow = (float4*)(out + (size_t)row * HID);
    orow[threadIdx.x]       = o0;
    orow[threadIdx.x + 256] = o1;
}

// ---------------------------------------------------------------------------
// SGEMM: C[M,N] = A[M,K] @ B[K,N] (+ D), row-major, M=4096 N=K=2048
// 128x128 tile, BK=8, 256 threads, 8x8 per-thread, register prefetch.
// ---------------------------------------------------------------------------
__global__ __launch_bounds__(256) void sgemm_kernel(
    const float* __restrict__ A, const float* __restrict__ B,
    const float* __restrict__ Dd, float* __restrict__ C)
{
    const int N = HID, K = HID;
    __shared__ float As[8][128];
    __shared__ float Bs[8][128];
    int bx = blockIdx.x * 128;
    int by = blockIdx.y * 128;
    int tid = threadIdx.x;
    int a_row = tid >> 1;
    int a_col = (tid & 1) << 2;
    int b_row = tid >> 5;
    int b_col = (tid & 31) << 2;
    const float* Abase = A + (size_t)(by + a_row) * K;
    const float* Bbase = B + (size_t)b_row * N + bx + b_col;
    int tx = tid & 15, ty = tid >> 4;

    float acc[8][8];
    #pragma unroll
    for (int i = 0; i < 8; i++)
        #pragma unroll
        for (int j = 0; j < 8; j++) acc[i][j] = 0.0f;

    float4 areg = *(const float4*)(Abase + a_col);
    float4 breg = *(const float4*)(Bbase);

    for (int k0 = 0; k0 < K; k0 += 8) {
        As[a_col + 0][a_row] = areg.x;
        As[a_col + 1][a_row] = areg.y;
        As[a_col + 2][a_row] = areg.z;
        As[a_col + 3][a_row] = areg.w;
        *(float4*)&Bs[b_row][b_col] = breg;
        __syncthreads();
        if (k0 + 8 < K) {
            areg = *(const float4*)(Abase + k0 + 8 + a_col);
            breg = *(const float4*)(Bbase + (size_t)(k0 + 8) * N);
        }
        #pragma unroll
        for (int kk = 0; kk < 8; kk++) {
            float ar[8], br[8];
            *(float4*)(ar + 0) = *(const float4*)&As[kk][ty * 8];
            *(float4*)(ar + 4) = *(const float4*)&As[kk][ty * 8 + 4];
            *(float4*)(br + 0) = *(const float4*)&Bs[kk][tx * 8];
            *(float4*)(br + 4) = *(const float4*)&Bs[kk][tx * 8 + 4];
            #pragma unroll
            for (int i = 0; i < 8; i++)
                #pragma unroll
                for (int j = 0; j < 8; j++)
                    acc[i][j] = fmaf(ar[i], br[j], acc[i][j]);
        }
        __syncthreads();
    }

    #pragma unroll
    for (int i = 0; i < 8; i++) {
        size_t row = (size_t)(by + ty * 8 + i);
        float* crow = C + row * N + bx + tx * 8;
        float4 c0 = make_float4(acc[i][0], acc[i][1], acc[i][2], acc[i][3]);
        float4 c1 = make_float4(acc[i][4], acc[i][5], acc[i][6], acc[i][7]);
        if (Dd) {
            const float* drow = Dd + row * N + bx + tx * 8;
            float4 d0 = *(const float4*)(drow);
            float4 d1 = *(const float4*)(drow + 4);
            c0.x += d0.x; c0.y += d0.y; c0.z += d0.z; c0.w += d0.w;
            c1.x += d1.x; c1.y += d1.y; c1.z += d1.z; c1.w += d1.w;
        }
        *(float4*)(crow)     = c0;
        *(float4*)(crow + 4) = c1;
    }
}

// ---------------------------------------------------------------------------
// RoPE applied in-place to Q and K. One block per token.
// ---------------------------------------------------------------------------
__global__ __launch_bounds__(256) void rope_kernel(float* q, float* k) {
    int token = blockIdx.x;
    int s = token & (SEQ - 1);
    float* qr = q + (size_t)token * HID;
    float* kr = k + (size_t)token * HID;
    for (int idx = threadIdx.x; idx < NHEADS * 64; idx += 256) {
        int h = idx >> 6, i = idx & 63;
        float c  = g_cos[s * 64 + i];
        float sn = g_sin[s * 64 + i];
        int o1 = h * HDIM + i, o2 = o1 + 64;
        float q1 = qr[o1], q2 = qr[o2];
        qr[o1] = q1 * c - q2 * sn;
        qr[o2] = q2 * c + q1 * sn;
        float k1 = kr[o1], k2 = kr[o2];
        kr[o1] = k1 * c - k2 * sn;
        kr[o2] = k2 * c + k1 * sn;
    }
}

// ---------------------------------------------------------------------------
// Flash attention, fp32. Bq=128 q-rows per block, Bk=64 per iteration.
// 256 threads: tx=tid&15 (4 k-cols / two 4-d-chunks), ty=tid>>4 (8 q-rows).
// smem operands stored transposed for conflict-free float4 LDS in mainloop.
// ---------------------------------------------------------------------------
#define BQ 128
#define BKT 64
#define QS 132
#define KS 68
#define VS 132
#define PS 132
#define ATTN_SMEM_BYTES ((128*QS + 128*KS + BKT*VS + BKT*PS) * 4)   // 166 KB

__global__ __launch_bounds__(256, 1) void attn_kernel(
    const float* __restrict__ q, const float* __restrict__ k,
    const float* __restrict__ v, float* __restrict__ out)
{
    extern __shared__ float sm[];
    float* Qst = sm;                 // [d=128][r=BQ]   stride QS
    float* Kst = Qst + 128 * QS;     // [d=128][c=BKT]  stride KS
    float* Vs  = Kst + 128 * KS;     // [c=BKT][d=128]  stride VS
    float* Pst = Vs  + BKT * VS;     // [c=BKT][r=BQ]   stride PS

    int tid = threadIdx.x;
    int tx = tid & 15, ty = tid >> 4;
    int b = blockIdx.z, hh = blockIdx.y, qb = blockIdx.x * BQ;
    const float scale = 0.08838834764831845f;   // 1/sqrt(128)

    const float* qbase = q + (size_t)(b * SEQ) * HID + hh * HDIM;
    const float* kbase = k + (size_t)(b * SEQ) * HID + hh * HDIM;
    const float* vbase = v + (size_t)(b * SEQ) * HID + hh * HDIM;

    for (int i = tid; i < BQ * HDIM; i += 256) {
        int r = i >> 7, d = i & 127;
        Qst[d * QS + r] = qbase[(size_t)(qb + r) * HID + d] * scale;
    }

    float m_prev[8], l_run[8];
    float o1[8][4], o2[8][4];
    #pragma unroll
    for (int i = 0; i < 8; i++) {
        m_prev[i] = -INFINITY; l_run[i] = 0.0f;
        #pragma unroll
        for (int j = 0; j < 4; j++) { o1[i][j] = 0.0f; o2[i][j] = 0.0f; }
    }
    int r0 = ty * 8, c0 = tx * 4;

    for (int kt = 0; kt < SEQ; kt += BKT) {
        __syncthreads();   // also covers Q-load on first iter
        for (int i = tid; i < BKT * HDIM; i += 256) {
            int c = i >> 7, d = i & 127;
            float kvld = kbase[(size_t)(kt + c) * HID + d];
            float vvld = vbase[(size_t)(kt + c) * HID + d];
            Kst[d * KS + c] = kvld;
            Vs[c * VS + d]  = vvld;
        }
        __syncthreads();

        // S = Q K^T tile (BQ x BKT), per-thread 8x4
        float sacc[8][4];
        #pragma unroll
        for (int i = 0; i < 8; i++)
            #pragma unroll
            for (int j = 0; j < 4; j++) sacc[i][j] = 0.0f;

        #pragma unroll 4
        for (int d = 0; d < HDIM; d++) {
            float4 qa  = *(const float4*)&Qst[d * QS + r0];
            float4 qb4 = *(const float4*)&Qst[d * QS + r0 + 4];
            float4 kv  = *(const float4*)&Kst[d * KS + c0];
            float qr[8] = {qa.x, qa.y, qa.z, qa.w, qb4.x, qb4.y, qb4.z, qb4.w};
            float krr[4] = {kv.x, kv.y, kv.z, kv.w};
            #pragma unroll
            for (int i = 0; i < 8; i++)
                #pragma unroll
                for (int j = 0; j < 4; j++)
                    sacc[i][j] = fmaf(qr[i], krr[j], sacc[i][j]);
        }

        // online softmax update (row stats replicated across the 16 tx lanes)
        #pragma unroll
        for (int i = 0; i < 8; i++) {
            float mt = fmaxf(fmaxf(sacc[i][0], sacc[i][1]), fmaxf(sacc[i][2], sacc[i][3]));
            #pragma unroll
            for (int m = 1; m < 16; m <<= 1) mt = fmaxf(mt, __shfl_xor_sync(0xffffffffu, mt, m));
            float mn = fmaxf(m_prev[i], mt);
            float alpha = __expf(m_prev[i] - mn);
            float rs = 0.0f;
            #pragma unroll
            for (int j = 0; j < 4; j++) {
                float p = __expf(sacc[i][j] - mn);
                sacc[i][j] = p; rs += p;
            }
            #pragma unroll
            for (int m = 1; m < 16; m <<= 1) rs += __shfl_xor_sync(0xffffffffu, rs, m);
            l_run[i] = l_run[i] * alpha + rs;
            m_prev[i] = mn;
            #pragma unroll
            for (int j = 0; j < 4; j++) { o1[i][j] *= alpha; o2[i][j] *= alpha; }
            #pragma unroll
            for (int j = 0; j < 4; j++) Pst[(c0 + j) * PS + r0 + i] = sacc[i][j];
        }
        __syncthreads();

        // O += P @ V  (per-thread rows r0..r0+7, d-cols {c0..c0+3, 64+c0..64+c0+3})
        #pragma unroll 4
        for (int kk = 0; kk < BKT; kk++) {
            float4 pA = *(const float4*)&Pst[kk * PS + r0];
            float4 pB = *(const float4*)&Pst[kk * PS + r0 + 4];
            float pr[8] = {pA.x, pA.y, pA.z, pA.w, pB.x, pB.y, pB.z, pB.w};
            float4 v1 = *(const float4*)&Vs[kk * VS + c0];
            float4 v2 = *(const float4*)&Vs[kk * VS + 64 + c0];
            #pragma unroll
            for (int i = 0; i < 8; i++) {
                o1[i][0] = fmaf(pr[i], v1.x, o1[i][0]);
                o1[i][1] = fmaf(pr[i], v1.y, o1[i][1]);
                o1[i][2] = fmaf(pr[i], v1.z, o1[i][2]);
                o1[i][3] = fmaf(pr[i], v1.w, o1[i][3]);
                o2[i][0] = fmaf(pr[i], v2.x, o2[i][0]);
                o2[i][1] = fmaf(pr[i], v2.y, o2[i][1]);
                o2[i][2] = fmaf(pr[i], v2.z, o2[i][2]);
                o2[i][3] = fmaf(pr[i], v2.w, o2[i][3]);
            }
        }
    }

    float* obase = out + (size_t)(b * SEQ) * HID + hh * HDIM;
    #pragma unroll
    for (int i = 0; i < 8; i++) {
        float inv = 1.0f / l_run[i];
        size_t row = (size_t)(qb + r0 + i) * HID;
        float4 w1v = make_float4(o1[i][0]*inv, o1[i][1]*inv, o1[i][2]*inv, o1[i][3]*inv);
        float4 w2v = make_float4(o2[i][0]*inv, o2[i][1]*inv, o2[i][2]*inv, o2[i][3]*inv);
        *(float4*)&obase[row + c0]      = w1v;
        *(float4*)&obase[row + 64 + c0] = w2v;
    }
}

// ---------------------------------------------------------------------------
// g1 = silu(g1) * g3
// ---------------------------------------------------------------------------
__global__ __launch_bounds__(256) void silu_mul_kernel(float* g1, const float* __restrict__ g3) {
    int i = blockIdx.x * 256 + threadIdx.x;
    if (i < MROWS * HID) {
        float a = g1[i];
        float s = a / (1.0f + expf(-a));
        g1[i] = s * g3[i];
    }
}

// ---------------------------------------------------------------------------
// Launch
// ---------------------------------------------------------------------------
extern "C" void kernel_launch(void* const* d_in, const int* in_sizes, int n_in,
                              void* d_out, int out_size)
{
    (void)in_sizes; (void)n_in; (void)out_size;
    const float* hs  = (const float*)d_in[0];
    const float* Wq  = (const float*)d_in[1];
    const float* Wk  = (const float*)d_in[2];
    const float* Wv  = (const float*)d_in[3];
    const float* Wo  = (const float*)d_in[4];
    const float* w1  = (const float*)d_in[5];
    const float* w2  = (const float*)d_in[6];
    const float* w3  = (const float*)d_in[7];
    const float* ln1 = (const float*)d_in[8];
    const float* ln2 = (const float*)d_in[9];
    float* out = (float*)d_out;

    float *xn, *q, *k, *v, *ctx, *h, *y, *g1, *g3;
    cudaGetSymbolAddress((void**)&xn,  g_xn);
    cudaGetSymbolAddress((void**)&q,   g_q);
    cudaGetSymbolAddress((void**)&k,   g_k);
    cudaGetSymbolAddress((void**)&v,   g_v);
    cudaGetSymbolAddress((void**)&ctx, g_ctx);
    cudaGetSymbolAddress((void**)&h,   g_h);
    cudaGetSymbolAddress((void**)&y,   g_y);
    cudaGetSymbolAddress((void**)&g1,  g_g1);
    cudaGetSymbolAddress((void**)&g3,  g_g3);

    cudaFuncSetAttribute(attn_kernel, cudaFuncAttributeMaxDynamicSharedMemorySize, ATTN_SMEM_BYTES);

    dim3 gemm_grid(HID / 128, MROWS / 128);   // (16, 32)

    rope_table_kernel<<<(SEQ * 64 + 255) / 256, 256>>>();
    rmsnorm_kernel<<<MROWS, 256>>>(hs, ln1, xn);

    sgemm_kernel<<<gemm_grid, 256>>>(xn, Wq, nullptr, q);
    sgemm_kernel<<<gemm_grid, 256>>>(xn, Wk, nullptr, k);
    sgemm_kernel<<<gemm_grid, 256>>>(xn, Wv, nullptr, v);

    rope_kernel<<<MROWS, 256>>>(q, k);

    attn_kernel<<<dim3(SEQ / BQ, NHEADS, BATCH), 256, ATTN_SMEM_BYTES>>>(q, k, v, ctx);

    sgemm_kernel<<<gemm_grid, 256>>>(ctx, Wo, hs, h);       // h = residual + attn_out
    rmsnorm_kernel<<<MROWS, 256>>>(h, ln2, y);

    sgemm_kernel<<<gemm_grid, 256>>>(y, w1, nullptr, g1);
    sgemm_kernel<<<gemm_grid, 256>>>(y, w3, nullptr, g3);
    silu_mul_kernel<<<(MROWS * HID + 255) / 256, 256>>>(g1, g3);

    sgemm_kernel<<<gemm_grid, 256>>>(g1, w2, h, out);       // out = h + mlp
}

// round 4
// speedup vs baseline: 1.7535x; 1.7535x over previous
#include <cuda_runtime.h>
#include <cuda_bf16.h>
#include <math.h>
#include <stdint.h>

// Problem constants
#define BATCH   2
#define SEQ     2048
#define HID     2048
#define NHEADS  16
#define HDIM    128
#define MROWS   (BATCH*SEQ)        // 4096
#define EPSV    1e-6f
#define KTOT    (3*HID)            // 6144 bf16: A=[hi|hi|lo], B=[hi|lo|hi]

typedef __nv_bfloat16 bf16;
typedef __nv_bfloat162 bf162;

// ---------------------------------------------------------------------------
// Scratch (__device__ globals; no cudaMalloc allowed)
// ---------------------------------------------------------------------------
__device__ bf16 g_xn3 [MROWS*KTOT];
__device__ bf16 g_ctx3[MROWS*KTOT];
__device__ bf16 g_g13 [MROWS*KTOT];
__device__ bf16 g_Wq3[HID*KTOT];
__device__ bf16 g_Wk3[HID*KTOT];
__device__ bf16 g_Wv3[HID*KTOT];
__device__ bf16 g_Wo3[HID*KTOT];
__device__ bf16 g_w13[HID*KTOT];
__device__ bf16 g_w23[HID*KTOT];
__device__ bf16 g_w33[HID*KTOT];
__device__ float g_q  [MROWS*HID];
__device__ float g_k  [MROWS*HID];
__device__ float g_v  [MROWS*HID];
__device__ float g_ctx[MROWS*HID];
__device__ float g_h  [MROWS*HID];
__device__ float g_g1 [MROWS*HID];
__device__ float g_g3 [MROWS*HID];
__device__ float g_cos[SEQ*64];
__device__ float g_sin[SEQ*64];

// ---------------------------------------------------------------------------
// Helpers
// ---------------------------------------------------------------------------
__device__ __forceinline__ uint32_t smem_u32(const void* p) {
    uint32_t a;
    asm("{ .reg .u64 t; cvta.to.shared.u64 t, %1; cvt.u32.u64 %0, t; }" : "=r"(a) : "l"(p));
    return a;
}
__device__ __forceinline__ void bf16split(float x, bf16& hi, bf16& lo) {
    hi = __float2bfloat16(x);
    lo = __float2bfloat16(x - __bfloat162float(hi));
}
__device__ __forceinline__ void cpasync16(uint32_t dst, const void* src) {
    asm volatile("cp.async.cg.shared.global [%0], [%1], 16;" :: "r"(dst), "l"(src));
}
__device__ __forceinline__ void ldm_x4(uint32_t& r0, uint32_t& r1, uint32_t& r2, uint32_t& r3,
                                       uint32_t addr) {
    asm volatile("ldmatrix.sync.aligned.m8n8.x4.shared.b16 {%0,%1,%2,%3}, [%4];"
                 : "=r"(r0), "=r"(r1), "=r"(r2), "=r"(r3) : "r"(addr));
}
__device__ __forceinline__ void mma16816(float* c, const uint32_t* a, const uint32_t* b) {
    asm volatile(
        "mma.sync.aligned.m16n8k16.row.col.f32.bf16.bf16.f32 "
        "{%0,%1,%2,%3}, {%4,%5,%6,%7}, {%8,%9}, {%0,%1,%2,%3};"
        : "+f"(c[0]), "+f"(c[1]), "+f"(c[2]), "+f"(c[3])
        : "r"(a[0]), "r"(a[1]), "r"(a[2]), "r"(a[3]), "r"(b[0]), "r"(b[1]));
}

// ---------------------------------------------------------------------------
// RoPE cos/sin table
// ---------------------------------------------------------------------------
__global__ void rope_table_kernel() {
    int idx = blockIdx.x * 256 + threadIdx.x;
    if (idx < SEQ * 64) {
        int s = idx >> 6, i = idx & 63;
        double inv = pow(10000.0, -((double)(2 * i)) / 128.0);
        double ang = (double)s * inv;
        g_cos[idx] = (float)cos(ang);
        g_sin[idx] = (float)sin(ang);
    }
}

// ---------------------------------------------------------------------------
// RMSNorm fused with bf16 double-split: out3[r] = [hi | hi | lo] (6144 bf16)
// ---------------------------------------------------------------------------
__global__ __launch_bounds__(256) void rmsnorm_split_kernel(
    const float* __restrict__ x, const float* __restrict__ w, bf16* __restrict__ out3)
{
    int row = blockIdx.x;
    const float4* xr = (const float4*)(x + (size_t)row * HID);
    float4 v0 = xr[threadIdx.x];
    float4 v1 = xr[threadIdx.x + 256];
    float ss = v0.x*v0.x + v0.y*v0.y + v0.z*v0.z + v0.w*v0.w
             + v1.x*v1.x + v1.y*v1.y + v1.z*v1.z + v1.w*v1.w;
    #pragma unroll
    for (int m = 16; m; m >>= 1) ss += __shfl_xor_sync(0xffffffffu, ss, m);
    __shared__ float red[8];
    if ((threadIdx.x & 31) == 0) red[threadIdx.x >> 5] = ss;
    __syncthreads();
    float tot = red[0] + red[1] + red[2] + red[3] + red[4] + red[5] + red[6] + red[7];
    float sc = rsqrtf(tot * (1.0f / (float)HID) + EPSV);
    const float4* wv = (const float4*)w;
    float4 w0 = wv[threadIdx.x];
    float4 w1v = wv[threadIdx.x + 256];
    float o[8] = { v0.x*sc*w0.x,  v0.y*sc*w0.y,  v0.z*sc*w0.z,  v0.w*sc*w0.w,
                   v1.x*sc*w1v.x, v1.y*sc*w1v.y, v1.z*sc*w1v.z, v1.w*sc*w1v.w };
    bf16 hi[8], lo[8];
    #pragma unroll
    for (int i = 0; i < 8; i++) bf16split(o[i], hi[i], lo[i]);
    bf16* orow = out3 + (size_t)row * KTOT;
    int c0 = threadIdx.x * 4, c1 = c0 + 1024;
    bf162 h0a = {hi[0], hi[1]}, h0b = {hi[2], hi[3]};
    bf162 h1a = {hi[4], hi[5]}, h1b = {hi[6], hi[7]};
    bf162 l0a = {lo[0], lo[1]}, l0b = {lo[2], lo[3]};
    bf162 l1a = {lo[4], lo[5]}, l1b = {lo[6], lo[7]};
    #define ST2(off, a, b) { bf162* p = (bf162*)&orow[off]; p[0] = a; p[1] = b; }
    ST2(c0,        h0a, h0b)  ST2(c1,        h1a, h1b)
    ST2(c0 + 2048, h0a, h0b)  ST2(c1 + 2048, h1a, h1b)
    ST2(c0 + 4096, l0a, l0b)  ST2(c1 + 4096, l1a, l1b)
    #undef ST2
}

// ---------------------------------------------------------------------------
// Plain A-split (for ctx): x[R x 2048] fp32 -> out3[R x 6144] bf16 [hi|hi|lo]
// ---------------------------------------------------------------------------
__global__ __launch_bounds__(256) void asplit_kernel(
    const float* __restrict__ x, bf16* __restrict__ out3)
{
    int i = blockIdx.x * 256 + threadIdx.x;   // float4 index
    if (i >= MROWS * HID / 4) return;
    int row = i / (HID/4), col4 = i % (HID/4);
    float4 v = ((const float4*)x)[i];
    bf16 hx,lx,hy,ly,hz,lz,hw,lw;
    bf16split(v.x,hx,lx); bf16split(v.y,hy,ly); bf16split(v.z,hz,lz); bf16split(v.w,hw,lw);
    bf16* orow = out3 + (size_t)row * KTOT + col4*4;
    bf162 ha = {hx,hy}, hb = {hz,hw}, la = {lx,ly}, lb = {lz,lw};
    #define ST2(off, a, b) { bf162* p = (bf162*)&orow[off]; p[0] = a; p[1] = b; }
    ST2(0, ha, hb)  ST2(2048, ha, hb)  ST2(4096, la, lb)
    #undef ST2
}

// ---------------------------------------------------------------------------
// Weight transpose+split: W[K=2048][N=2048] f32 -> B3[N][6144] bf16 [hi|lo|hi]
// ---------------------------------------------------------------------------
__global__ __launch_bounds__(256) void wsplit_kernel(
    const float* __restrict__ W, bf16* __restrict__ B3)
{
    __shared__ float t[32][33];
    int bn = blockIdx.x * 32;   // n-tile
    int bk = blockIdx.y * 32;   // k-tile
    int tx = threadIdx.x & 31, ty = threadIdx.x >> 5;  // 32 x 8
    #pragma unroll
    for (int i = 0; i < 4; i++)
        t[ty + 8*i][tx] = W[(size_t)(bk + ty + 8*i) * HID + bn + tx];
    __syncthreads();
    #pragma unroll
    for (int i = 0; i < 4; i++) {
        int n = bn + ty + 8*i;
        int k = bk + tx;
        float v = t[tx][ty + 8*i];
        bf16 hi, lo; bf16split(v, hi, lo);
        bf16* orow = B3 + (size_t)n * KTOT;
        orow[k]        = hi;
        orow[k + 2048] = lo;
        orow[k + 4096] = hi;
    }
}

// ---------------------------------------------------------------------------
// HMMA bf16 GEMM: C[4096 x 2048] = A3[4096 x 6144] @ B3[2048 x 6144]^T (+Dd)
// mma.sync.m16n8k16 + ldmatrix + 4-stage cp.async. Tile 128x128, BK=32.
// 8 warps: warp_m = wid&1 (64 rows), warp_n = wid>>1 (32 cols).
// smem rows padded to 40 halves (80B) -> 16B-aligned & conflict-free ldmatrix.
// ---------------------------------------------------------------------------
#define ASTRIDE 40
#define STG_HALVES (128*ASTRIDE)            // per operand per stage
#define STGB ((STG_HALVES*2)*2)             // A+B bytes per stage = 20480
#define NSTG 4
#define GEMM_SMEM (NSTG*STGB)               // 81920
#define KITERS (KTOT/32)                    // 192

__global__ __launch_bounds__(256, 2) void hmma_gemm_kernel(
    const bf16* __restrict__ A3, const bf16* __restrict__ B3,
    const float* __restrict__ Dd, float* __restrict__ C)
{
    extern __shared__ char smraw[];
    uint32_t smb = smem_u32(smraw);
    int tid = threadIdx.x, wid = tid >> 5, lid = tid & 31;
    int mt = blockIdx.x, nt = blockIdx.y;

    // ---- load mapping: 2 A rows + 2 B rows per thread, 16B each
    int lrow0 = tid >> 2, lrow1 = lrow0 + 64;
    int seg = tid & 3;
    const bf16* aptr0 = A3 + (size_t)(mt*128 + lrow0) * KTOT + seg*8;
    const bf16* aptr1 = A3 + (size_t)(mt*128 + lrow1) * KTOT + seg*8;
    const bf16* bptr0 = B3 + (size_t)(nt*128 + lrow0) * KTOT + seg*8;
    const bf16* bptr1 = B3 + (size_t)(nt*128 + lrow1) * KTOT + seg*8;
    uint32_t aoff0 = (uint32_t)(lrow0*ASTRIDE + seg*8) * 2;
    uint32_t aoff1 = (uint32_t)(lrow1*ASTRIDE + seg*8) * 2;
    uint32_t boff0 = (uint32_t)(STG_HALVES + lrow0*ASTRIDE + seg*8) * 2;
    uint32_t boff1 = (uint32_t)(STG_HALVES + lrow1*ASTRIDE + seg*8) * 2;

    #define LOADIT(it_) do {                                            \
        uint32_t sb_ = smb + (uint32_t)((it_) & 3) * STGB;              \
        int k0_ = (it_) * 32;                                           \
        cpasync16(sb_ + aoff0, aptr0 + k0_);                            \
        cpasync16(sb_ + aoff1, aptr1 + k0_);                            \
        cpasync16(sb_ + boff0, bptr0 + k0_);                            \
        cpasync16(sb_ + boff1, bptr1 + k0_);                            \
    } while (0)

    // ---- ldmatrix per-lane base offsets (halves)
    int m0w = (wid & 1) * 64, n0w = (wid >> 1) * 32;
    int g = lid >> 3, r = lid & 7;
    // A x4 groups: (m0+r,k0) (m0+8+r,k0) (m0+r,k0+8) (m0+8+r,k0+8)
    uint32_t aBaseH = (uint32_t)((m0w + r + (g & 1)*8) * ASTRIDE + (g >> 1)*8);
    // B x4 groups: (n0+r,k0) (n0+r,k0+8) (n0+8+r,k0) (n0+8+r,k0+8)
    uint32_t bBaseH = (uint32_t)(STG_HALVES + (n0w + r + (g >> 1)*8) * ASTRIDE + (g & 1)*8);

    float acc[4][4][4];
    #pragma unroll
    for (int mi = 0; mi < 4; mi++)
        #pragma unroll
        for (int ni = 0; ni < 4; ni++)
            #pragma unroll
            for (int e = 0; e < 4; e++) acc[mi][ni][e] = 0.0f;

    // ---- prefetch 3 stages
    #pragma unroll
    for (int s = 0; s < 3; s++) {
        LOADIT(s);
        asm volatile("cp.async.commit_group;");
    }

    for (int it = 0; it < KITERS; it++) {
        asm volatile("cp.async.wait_group 2;");
        __syncthreads();
        uint32_t sb = smb + (uint32_t)(it & 3) * STGB;
        #pragma unroll
        for (int ks = 0; ks < 32; ks += 16) {
            uint32_t b[4][2];
            #pragma unroll
            for (int np = 0; np < 2; np++) {
                uint32_t r0, r1, r2, r3;
                ldm_x4(r0, r1, r2, r3, sb + 2*(bBaseH + (uint32_t)(np*16*ASTRIDE) + ks));
                b[np*2][0] = r0;   b[np*2][1] = r1;
                b[np*2+1][0] = r2; b[np*2+1][1] = r3;
            }
            #pragma unroll
            for (int mi = 0; mi < 4; mi++) {
                uint32_t a[4];
                ldm_x4(a[0], a[1], a[2], a[3], sb + 2*(aBaseH + (uint32_t)(mi*16*ASTRIDE) + ks));
                #pragma unroll
                for (int ni = 0; ni < 4; ni++) mma16816(acc[mi][ni], a, b[ni]);
            }
        }
        int itn = it + 3;
        if (itn < KITERS) LOADIT(itn);
        asm volatile("cp.async.commit_group;");
    }

    // ---- epilogue
    int lr = lid >> 2, lc = (lid & 3) * 2;
    #pragma unroll
    for (int mi = 0; mi < 4; mi++) {
        #pragma unroll
        for (int ni = 0; ni < 4; ni++) {
            int row0 = mt*128 + m0w + mi*16 + lr;
            int col  = nt*128 + n0w + ni*8 + lc;
            float2 v0 = make_float2(acc[mi][ni][0], acc[mi][ni][1]);
            float2 v1 = make_float2(acc[mi][ni][2], acc[mi][ni][3]);
            if (Dd) {
                float2 d0 = *(const float2*)(Dd + (size_t)row0 * HID + col);
                float2 d1 = *(const float2*)(Dd + (size_t)(row0 + 8) * HID + col);
                v0.x += d0.x; v0.y += d0.y;
                v1.x += d1.x; v1.y += d1.y;
            }
            *(float2*)(C + (size_t)row0 * HID + col)       = v0;
            *(float2*)(C + (size_t)(row0 + 8) * HID + col) = v1;
        }
    }
    #undef LOADIT
}

// ---------------------------------------------------------------------------
// RoPE applied in-place to Q and K. One block per token.
// ---------------------------------------------------------------------------
__global__ __launch_bounds__(256) void rope_kernel(float* q, float* k) {
    int token = blockIdx.x;
    int s = token & (SEQ - 1);
    float* qr = q + (size_t)token * HID;
    float* kr = k + (size_t)token * HID;
    for (int idx = threadIdx.x; idx < NHEADS * 64; idx += 256) {
        int h = idx >> 6, i = idx & 63;
        float c  = g_cos[s * 64 + i];
        float sn = g_sin[s * 64 + i];
        int o1 = h * HDIM + i, o2 = o1 + 64;
        float q1 = qr[o1], q2 = qr[o2];
        qr[o1] = q1 * c - q2 * sn;
        qr[o2] = q2 * c + q1 * sn;
        float k1 = kr[o1], k2 = kr[o2];
        kr[o1] = k1 * c - k2 * sn;
        kr[o2] = k2 * c + k1 * sn;
    }
}

// ---------------------------------------------------------------------------
// Flash attention, fp32 (proven in R0/R1)
// ---------------------------------------------------------------------------
#define BQ 128
#define BKT 64
#define QS 132
#define KS 68
#define VS 132
#define PS 132
#define ATTN_SMEM_BYTES ((128*QS + 128*KS + BKT*VS + BKT*PS) * 4)

__global__ __launch_bounds__(256, 1) void attn_kernel(
    const float* __restrict__ q, const float* __restrict__ k,
    const float* __restrict__ v, float* __restrict__ out)
{
    extern __shared__ float sm[];
    float* Qst = sm;
    float* Kst = Qst + 128 * QS;
    float* Vs  = Kst + 128 * KS;
    float* Pst = Vs  + BKT * VS;

    int tid = threadIdx.x;
    int tx = tid & 15, ty = tid >> 4;
    int b = blockIdx.z, hh = blockIdx.y, qb = blockIdx.x * BQ;
    const float scale = 0.08838834764831845f;

    const float* qbase = q + (size_t)(b * SEQ) * HID + hh * HDIM;
    const float* kbase = k + (size_t)(b * SEQ) * HID + hh * HDIM;
    const float* vbase = v + (size_t)(b * SEQ) * HID + hh * HDIM;

    for (int i = tid; i < BQ * HDIM; i += 256) {
        int r = i >> 7, d = i & 127;
        Qst[d * QS + r] = qbase[(size_t)(qb + r) * HID + d] * scale;
    }

    float m_prev[8], l_run[8];
    float o1[8][4], o2[8][4];
    #pragma unroll
    for (int i = 0; i < 8; i++) {
        m_prev[i] = -INFINITY; l_run[i] = 0.0f;
        #pragma unroll
        for (int j = 0; j < 4; j++) { o1[i][j] = 0.0f; o2[i][j] = 0.0f; }
    }
    int r0 = ty * 8, c0 = tx * 4;

    for (int kt = 0; kt < SEQ; kt += BKT) {
        __syncthreads();
        for (int i = tid; i < BKT * HDIM; i += 256) {
            int c = i >> 7, d = i & 127;
            float kvld = kbase[(size_t)(kt + c) * HID + d];
            float vvld = vbase[(size_t)(kt + c) * HID + d];
            Kst[d * KS + c] = kvld;
            Vs[c * VS + d]  = vvld;
        }
        __syncthreads();

        float sacc[8][4];
        #pragma unroll
        for (int i = 0; i < 8; i++)
            #pragma unroll
            for (int j = 0; j < 4; j++) sacc[i][j] = 0.0f;

        #pragma unroll 4
        for (int d = 0; d < HDIM; d++) {
            float4 qa  = *(const float4*)&Qst[d * QS + r0];
            float4 qb4 = *(const float4*)&Qst[d * QS + r0 + 4];
            float4 kv  = *(const float4*)&Kst[d * KS + c0];
            float qr[8] = {qa.x, qa.y, qa.z, qa.w, qb4.x, qb4.y, qb4.z, qb4.w};
            float krr[4] = {kv.x, kv.y, kv.z, kv.w};
            #pragma unroll
            for (int i = 0; i < 8; i++)
                #pragma unroll
                for (int j = 0; j < 4; j++)
                    sacc[i][j] = fmaf(qr[i], krr[j], sacc[i][j]);
        }

        #pragma unroll
        for (int i = 0; i < 8; i++) {
            float mt = fmaxf(fmaxf(sacc[i][0], sacc[i][1]), fmaxf(sacc[i][2], sacc[i][3]));
            #pragma unroll
            for (int m = 1; m < 16; m <<= 1) mt = fmaxf(mt, __shfl_xor_sync(0xffffffffu, mt, m));
            float mn = fmaxf(m_prev[i], mt);
            float alpha = __expf(m_prev[i] - mn);
            float rs = 0.0f;
            #pragma unroll
            for (int j = 0; j < 4; j++) {
                float p = __expf(sacc[i][j] - mn);
                sacc[i][j] = p; rs += p;
            }
            #pragma unroll
            for (int m = 1; m < 16; m <<= 1) rs += __shfl_xor_sync(0xffffffffu, rs, m);
            l_run[i] = l_run[i] * alpha + rs;
            m_prev[i] = mn;
            #pragma unroll
            for (int j = 0; j < 4; j++) { o1[i][j] *= alpha; o2[i][j] *= alpha; }
            #pragma unroll
            for (int j = 0; j < 4; j++) Pst[(c0 + j) * PS + r0 + i] = sacc[i][j];
        }
        __syncthreads();

        #pragma unroll 4
        for (int kk = 0; kk < BKT; kk++) {
            float4 pA = *(const float4*)&Pst[kk * PS + r0];
            float4 pB = *(const float4*)&Pst[kk * PS + r0 + 4];
            float pr[8] = {pA.x, pA.y, pA.z, pA.w, pB.x, pB.y, pB.z, pB.w};
            float4 v1 = *(const float4*)&Vs[kk * VS + c0];
            float4 v2 = *(const float4*)&Vs[kk * VS + 64 + c0];
            #pragma unroll
            for (int i = 0; i < 8; i++) {
                o1[i][0] = fmaf(pr[i], v1.x, o1[i][0]);
                o1[i][1] = fmaf(pr[i], v1.y, o1[i][1]);
                o1[i][2] = fmaf(pr[i], v1.z, o1[i][2]);
                o1[i][3] = fmaf(pr[i], v1.w, o1[i][3]);
                o2[i][0] = fmaf(pr[i], v2.x, o2[i][0]);
                o2[i][1] = fmaf(pr[i], v2.y, o2[i][1]);
                o2[i][2] = fmaf(pr[i], v2.z, o2[i][2]);
                o2[i][3] = fmaf(pr[i], v2.w, o2[i][3]);
            }
        }
    }

    float* obase = out + (size_t)(b * SEQ) * HID + hh * HDIM;
    #pragma unroll
    for (int i = 0; i < 8; i++) {
        float inv = 1.0f / l_run[i];
        size_t row = (size_t)(qb + r0 + i) * HID;
        float4 w1v = make_float4(o1[i][0]*inv, o1[i][1]*inv, o1[i][2]*inv, o1[i][3]*inv);
        float4 w2v = make_float4(o2[i][0]*inv, o2[i][1]*inv, o2[i][2]*inv, o2[i][3]*inv);
        *(float4*)&obase[row + c0]      = w1v;
        *(float4*)&obase[row + 64 + c0] = w2v;
    }
}

// ---------------------------------------------------------------------------
// silu(g1)*g3 fused with bf16 split -> out3 [R x 6144] = [hi | hi | lo]
// ---------------------------------------------------------------------------
__global__ __launch_bounds__(256) void silu_split_kernel(
    const float* __restrict__ g1, const float* __restrict__ g3, bf16* __restrict__ out3)
{
    int i = blockIdx.x * 256 + threadIdx.x;  // float4 index
    if (i >= MROWS * HID / 4) return;
    int row = i / (HID/4), col4 = i % (HID/4);
    float4 a = ((const float4*)g1)[i];
    float4 b = ((const float4*)g3)[i];
    float4 v;
    v.x = (a.x / (1.0f + expf(-a.x))) * b.x;
    v.y = (a.y / (1.0f + expf(-a.y))) * b.y;
    v.z = (a.z / (1.0f + expf(-a.z))) * b.z;
    v.w = (a.w / (1.0f + expf(-a.w))) * b.w;
    bf16 hx,lx,hy,ly,hz,lz,hw,lw;
    bf16split(v.x,hx,lx); bf16split(v.y,hy,ly); bf16split(v.z,hz,lz); bf16split(v.w,hw,lw);
    bf16* orow = out3 + (size_t)row * KTOT + col4*4;
    bf162 ha = {hx,hy}, hb = {hz,hw}, la = {lx,ly}, lb = {lz,lw};
    #define ST2(off, a_, b_) { bf162* p = (bf162*)&orow[off]; p[0] = a_; p[1] = b_; }
    ST2(0, ha, hb)  ST2(2048, ha, hb)  ST2(4096, la, lb)
    #undef ST2
}

// ---------------------------------------------------------------------------
// Launch
// ---------------------------------------------------------------------------
extern "C" void kernel_launch(void* const* d_in, const int* in_sizes, int n_in,
                              void* d_out, int out_size)
{
    (void)in_sizes; (void)n_in; (void)out_size;
    const float* hs  = (const float*)d_in[0];
    const float* Wq  = (const float*)d_in[1];
    const float* Wk  = (const float*)d_in[2];
    const float* Wv  = (const float*)d_in[3];
    const float* Wo  = (const float*)d_in[4];
    const float* w1  = (const float*)d_in[5];
    const float* w2  = (const float*)d_in[6];
    const float* w3  = (const float*)d_in[7];
    const float* ln1 = (const float*)d_in[8];
    const float* ln2 = (const float*)d_in[9];
    float* out = (float*)d_out;

    bf16 *xn3, *ctx3, *g13;
    bf16 *Wq3, *Wk3, *Wv3, *Wo3, *w13, *w23, *w33;
    float *q, *k, *v, *ctx, *h, *g1, *g3;
    cudaGetSymbolAddress((void**)&xn3,  g_xn3);
    cudaGetSymbolAddress((void**)&ctx3, g_ctx3);
    cudaGetSymbolAddress((void**)&g13,  g_g13);
    cudaGetSymbolAddress((void**)&Wq3,  g_Wq3);
    cudaGetSymbolAddress((void**)&Wk3,  g_Wk3);
    cudaGetSymbolAddress((void**)&Wv3,  g_Wv3);
    cudaGetSymbolAddress((void**)&Wo3,  g_Wo3);
    cudaGetSymbolAddress((void**)&w13,  g_w13);
    cudaGetSymbolAddress((void**)&w23,  g_w23);
    cudaGetSymbolAddress((void**)&w33,  g_w33);
    cudaGetSymbolAddress((void**)&q,    g_q);
    cudaGetSymbolAddress((void**)&k,    g_k);
    cudaGetSymbolAddress((void**)&v,    g_v);
    cudaGetSymbolAddress((void**)&ctx,  g_ctx);
    cudaGetSymbolAddress((void**)&h,    g_h);
    cudaGetSymbolAddress((void**)&g1,   g_g1);
    cudaGetSymbolAddress((void**)&g3,   g_g3);

    cudaFuncSetAttribute(attn_kernel, cudaFuncAttributeMaxDynamicSharedMemorySize, ATTN_SMEM_BYTES);
    cudaFuncSetAttribute(hmma_gemm_kernel, cudaFuncAttributeMaxDynamicSharedMemorySize, GEMM_SMEM);

    dim3 gemm_grid(MROWS / 128, HID / 128);      // (32, 16)
    dim3 wgrid(HID / 32, HID / 32);              // (64, 64)
    int nv4 = MROWS * HID / 4;

    rope_table_kernel<<<(SEQ * 64 + 255) / 256, 256>>>();

    // weight transpose + bf16 double-split
    wsplit_kernel<<<wgrid, 256>>>(Wq, Wq3);
    wsplit_kernel<<<wgrid, 256>>>(Wk, Wk3);
    wsplit_kernel<<<wgrid, 256>>>(Wv, Wv3);
    wsplit_kernel<<<wgrid, 256>>>(Wo, Wo3);
    wsplit_kernel<<<wgrid, 256>>>(w1, w13);
    wsplit_kernel<<<wgrid, 256>>>(w2, w23);
    wsplit_kernel<<<wgrid, 256>>>(w3, w33);

    rmsnorm_split_kernel<<<MROWS, 256>>>(hs, ln1, xn3);

    hmma_gemm_kernel<<<gemm_grid, 256, GEMM_SMEM>>>(xn3, Wq3, nullptr, q);
    hmma_gemm_kernel<<<gemm_grid, 256, GEMM_SMEM>>>(xn3, Wk3, nullptr, k);
    hmma_gemm_kernel<<<gemm_grid, 256, GEMM_SMEM>>>(xn3, Wv3, nullptr, v);

    rope_kernel<<<MROWS, 256>>>(q, k);

    attn_kernel<<<dim3(SEQ / BQ, NHEADS, BATCH), 256, ATTN_SMEM_BYTES>>>(q, k, v, ctx);

    asplit_kernel<<<(nv4 + 255) / 256, 256>>>(ctx, ctx3);
    hmma_gemm_kernel<<<gemm_grid, 256, GEMM_SMEM>>>(ctx3, Wo3, hs, h);   // h = hs + ctx@Wo

    rmsnorm_split_kernel<<<MROWS, 256>>>(h, ln2, xn3);                   // reuse xn3 as y3

    hmma_gemm_kernel<<<gemm_grid, 256, GEMM_SMEM>>>(xn3, w13, nullptr, g1);
    hmma_gemm_kernel<<<gemm_grid, 256, GEMM_SMEM>>>(xn3, w33, nullptr, g3);

    silu_split_kernel<<<(nv4 + 255) / 256, 256>>>(g1, g3, g13);

    hmma_gemm_kernel<<<gemm_grid, 256, GEMM_SMEM>>>(g13, w23, h, out);   // out = h + mlp
}

// round 6
// speedup vs baseline: 2.7570x; 1.5723x over previous
#include <cuda_runtime.h>
#include <cuda_bf16.h>
#include <math.h>
#include <stdint.h>

// Problem constants
#define BATCH   2
#define SEQ     2048
#define HID     2048
#define NHEADS  16
#define HDIM    128
#define MROWS   (BATCH*SEQ)        // 4096
#define EPSV    1e-6f
#define KTOT    (3*HID)            // 6144 bf16: A=[hi|hi|lo], B=[hi|lo|hi]

typedef __nv_bfloat16 bf16;
typedef __nv_bfloat162 bf162;

// ---------------------------------------------------------------------------
// Scratch (__device__ globals; no cudaMalloc allowed)
// ---------------------------------------------------------------------------
__device__ bf16 g_xn3 [MROWS*KTOT];
__device__ bf16 g_ctx3[MROWS*KTOT];
__device__ bf16 g_g13 [MROWS*KTOT];
__device__ bf16 g_Wq3[HID*KTOT];
__device__ bf16 g_Wk3[HID*KTOT];
__device__ bf16 g_Wv3[HID*KTOT];
__device__ bf16 g_Wo3[HID*KTOT];
__device__ bf16 g_w13[HID*KTOT];
__device__ bf16 g_w23[HID*KTOT];
__device__ bf16 g_w33[HID*KTOT];
__device__ float g_q  [MROWS*HID];
__device__ float g_k  [MROWS*HID];
__device__ float g_v  [MROWS*HID];
__device__ float g_ctx[MROWS*HID];
__device__ float g_h  [MROWS*HID];
__device__ float g_g1 [MROWS*HID];
__device__ float g_g3 [MROWS*HID];
__device__ float g_cos[SEQ*64];
__device__ float g_sin[SEQ*64];
// attention operands (bf16 split, head-major)
__device__ bf16 g_q2 [(size_t)BATCH*NHEADS*SEQ*256];   // [bh][s][qh(128)|ql(128)]
__device__ bf16 g_k2 [(size_t)BATCH*NHEADS*SEQ*256];   // [bh][s][kh|kl]
__device__ bf16 g_vt [(size_t)BATCH*NHEADS*HDIM*2*SEQ];// [bh][d][vh(s) , vl at +SEQ]

// ---------------------------------------------------------------------------
// Helpers
// ---------------------------------------------------------------------------
__device__ __forceinline__ uint32_t smem_u32(const void* p) {
    uint32_t a;
    asm("{ .reg .u64 t; cvta.to.shared.u64 t, %1; cvt.u32.u64 %0, t; }" : "=r"(a) : "l"(p));
    return a;
}
__device__ __forceinline__ void bf16split(float x, bf16& hi, bf16& lo) {
    hi = __float2bfloat16(x);
    lo = __float2bfloat16(x - __bfloat162float(hi));
}
__device__ __forceinline__ uint32_t packsplit_hi(float x, float y) {
    bf162 t = { __float2bfloat16(x), __float2bfloat16(y) };
    return *(uint32_t*)&t;
}
__device__ __forceinline__ uint32_t packsplit_lo(float x, float y) {
    bf16 hx = __float2bfloat16(x), hy = __float2bfloat16(y);
    bf162 t = { __float2bfloat16(x - __bfloat162float(hx)),
                __float2bfloat16(y - __bfloat162float(hy)) };
    return *(uint32_t*)&t;
}
__device__ __forceinline__ void cpasync16(uint32_t dst, const void* src) {
    asm volatile("cp.async.cg.shared.global [%0], [%1], 16;" :: "r"(dst), "l"(src));
}
__device__ __forceinline__ void ldm_x4(uint32_t& r0, uint32_t& r1, uint32_t& r2, uint32_t& r3,
                                       uint32_t addr) {
    asm volatile("ldmatrix.sync.aligned.m8n8.x4.shared.b16 {%0,%1,%2,%3}, [%4];"
                 : "=r"(r0), "=r"(r1), "=r"(r2), "=r"(r3) : "r"(addr));
}
__device__ __forceinline__ void mma16816(float* c, const uint32_t* a, const uint32_t* b) {
    asm volatile(
        "mma.sync.aligned.m16n8k16.row.col.f32.bf16.bf16.f32 "
        "{%0,%1,%2,%3}, {%4,%5,%6,%7}, {%8,%9}, {%0,%1,%2,%3};"
        : "+f"(c[0]), "+f"(c[1]), "+f"(c[2]), "+f"(c[3])
        : "r"(a[0]), "r"(a[1]), "r"(a[2]), "r"(a[3]), "r"(b[0]), "r"(b[1]));
}

// ---------------------------------------------------------------------------
// RoPE cos/sin table
// ---------------------------------------------------------------------------
__global__ void rope_table_kernel() {
    int idx = blockIdx.x * 256 + threadIdx.x;
    if (idx < SEQ * 64) {
        int s = idx >> 6, i = idx & 63;
        double inv = pow(10000.0, -((double)(2 * i)) / 128.0);
        double ang = (double)s * inv;
        g_cos[idx] = (float)cos(ang);
        g_sin[idx] = (float)sin(ang);
    }
}

// ---------------------------------------------------------------------------
// RMSNorm fused with bf16 double-split: out3[r] = [hi | hi | lo] (6144 bf16)
// ---------------------------------------------------------------------------
__global__ __launch_bounds__(256) void rmsnorm_split_kernel(
    const float* __restrict__ x, const float* __restrict__ w, bf16* __restrict__ out3)
{
    int row = blockIdx.x;
    const float4* xr = (const float4*)(x + (size_t)row * HID);
    float4 v0 = xr[threadIdx.x];
    float4 v1 = xr[threadIdx.x + 256];
    float ss = v0.x*v0.x + v0.y*v0.y + v0.z*v0.z + v0.w*v0.w
             + v1.x*v1.x + v1.y*v1.y + v1.z*v1.z + v1.w*v1.w;
    #pragma unroll
    for (int m = 16; m; m >>= 1) ss += __shfl_xor_sync(0xffffffffu, ss, m);
    __shared__ float red[8];
    if ((threadIdx.x & 31) == 0) red[threadIdx.x >> 5] = ss;
    __syncthreads();
    float tot = red[0] + red[1] + red[2] + red[3] + red[4] + red[5] + red[6] + red[7];
    float sc = rsqrtf(tot * (1.0f / (float)HID) + EPSV);
    const float4* wv = (const float4*)w;
    float4 w0 = wv[threadIdx.x];
    float4 w1v = wv[threadIdx.x + 256];
    float o[8] = { v0.x*sc*w0.x,  v0.y*sc*w0.y,  v0.z*sc*w0.z,  v0.w*sc*w0.w,
                   v1.x*sc*w1v.x, v1.y*sc*w1v.y, v1.z*sc*w1v.z, v1.w*sc*w1v.w };
    bf16 hi[8], lo[8];
    #pragma unroll
    for (int i = 0; i < 8; i++) bf16split(o[i], hi[i], lo[i]);
    bf16* orow = out3 + (size_t)row * KTOT;
    int c0 = threadIdx.x * 4, c1 = c0 + 1024;
    bf162 h0a = {hi[0], hi[1]}, h0b = {hi[2], hi[3]};
    bf162 h1a = {hi[4], hi[5]}, h1b = {hi[6], hi[7]};
    bf162 l0a = {lo[0], lo[1]}, l0b = {lo[2], lo[3]};
    bf162 l1a = {lo[4], lo[5]}, l1b = {lo[6], lo[7]};
    #define ST2(off, a, b) { bf162* p = (bf162*)&orow[off]; p[0] = a; p[1] = b; }
    ST2(c0,        h0a, h0b)  ST2(c1,        h1a, h1b)
    ST2(c0 + 2048, h0a, h0b)  ST2(c1 + 2048, h1a, h1b)
    ST2(c0 + 4096, l0a, l0b)  ST2(c1 + 4096, l1a, l1b)
    #undef ST2
}

// ---------------------------------------------------------------------------
// Plain A-split (for ctx): x[R x 2048] fp32 -> out3[R x 6144] bf16 [hi|hi|lo]
// ---------------------------------------------------------------------------
__global__ __launch_bounds__(256) void asplit_kernel(
    const float* __restrict__ x, bf16* __restrict__ out3)
{
    int i = blockIdx.x * 256 + threadIdx.x;   // float4 index
    if (i >= MROWS * HID / 4) return;
    int row = i / (HID/4), col4 = i % (HID/4);
    float4 v = ((const float4*)x)[i];
    bf16 hx,lx,hy,ly,hz,lz,hw,lw;
    bf16split(v.x,hx,lx); bf16split(v.y,hy,ly); bf16split(v.z,hz,lz); bf16split(v.w,hw,lw);
    bf16* orow = out3 + (size_t)row * KTOT + col4*4;
    bf162 ha = {hx,hy}, hb = {hz,hw}, la = {lx,ly}, lb = {lz,lw};
    #define ST2(off, a, b) { bf162* p = (bf162*)&orow[off]; p[0] = a; p[1] = b; }
    ST2(0, ha, hb)  ST2(2048, ha, hb)  ST2(4096, la, lb)
    #undef ST2
}

// ---------------------------------------------------------------------------
// Weight transpose+split: W[K=2048][N=2048] f32 -> B3[N][6144] bf16 [hi|lo|hi]
// ---------------------------------------------------------------------------
__global__ __launch_bounds__(256) void wsplit_kernel(
    const float* __restrict__ W, bf16* __restrict__ B3)
{
    __shared__ float t[32][33];
    int bn = blockIdx.x * 32;   // n-tile
    int bk = blockIdx.y * 32;   // k-tile
    int tx = threadIdx.x & 31, ty = threadIdx.x >> 5;  // 32 x 8
    #pragma unroll
    for (int i = 0; i < 4; i++)
        t[ty + 8*i][tx] = W[(size_t)(bk + ty + 8*i) * HID + bn + tx];
    __syncthreads();
    #pragma unroll
    for (int i = 0; i < 4; i++) {
        int n = bn + ty + 8*i;
        int k = bk + tx;
        float v = t[tx][ty + 8*i];
        bf16 hi, lo; bf16split(v, hi, lo);
        bf16* orow = B3 + (size_t)n * KTOT;
        orow[k]        = hi;
        orow[k + 2048] = lo;
        orow[k + 4096] = hi;
    }
}

// ---------------------------------------------------------------------------
// HMMA bf16 GEMM (unchanged, proven in R4)
// ---------------------------------------------------------------------------
#define ASTRIDE 40
#define STG_HALVES (128*ASTRIDE)
#define STGB ((STG_HALVES*2)*2)
#define NSTG 4
#define GEMM_SMEM (NSTG*STGB)
#define KITERS (KTOT/32)

__global__ __launch_bounds__(256, 2) void hmma_gemm_kernel(
    const bf16* __restrict__ A3, const bf16* __restrict__ B3,
    const float* __restrict__ Dd, float* __restrict__ C)
{
    extern __shared__ char smraw[];
    uint32_t smb = smem_u32(smraw);
    int tid = threadIdx.x, wid = tid >> 5, lid = tid & 31;
    int mt = blockIdx.x, nt = blockIdx.y;

    int lrow0 = tid >> 2, lrow1 = lrow0 + 64;
    int seg = tid & 3;
    const bf16* aptr0 = A3 + (size_t)(mt*128 + lrow0) * KTOT + seg*8;
    const bf16* aptr1 = A3 + (size_t)(mt*128 + lrow1) * KTOT + seg*8;
    const bf16* bptr0 = B3 + (size_t)(nt*128 + lrow0) * KTOT + seg*8;
    const bf16* bptr1 = B3 + (size_t)(nt*128 + lrow1) * KTOT + seg*8;
    uint32_t aoff0 = (uint32_t)(lrow0*ASTRIDE + seg*8) * 2;
    uint32_t aoff1 = (uint32_t)(lrow1*ASTRIDE + seg*8) * 2;
    uint32_t boff0 = (uint32_t)(STG_HALVES + lrow0*ASTRIDE + seg*8) * 2;
    uint32_t boff1 = (uint32_t)(STG_HALVES + lrow1*ASTRIDE + seg*8) * 2;

    #define LOADIT(it_) do {                                            \
        uint32_t sb_ = smb + (uint32_t)((it_) & 3) * STGB;              \
        int k0_ = (it_) * 32;                                           \
        cpasync16(sb_ + aoff0, aptr0 + k0_);                            \
        cpasync16(sb_ + aoff1, aptr1 + k0_);                            \
        cpasync16(sb_ + boff0, bptr0 + k0_);                            \
        cpasync16(sb_ + boff1, bptr1 + k0_);                            \
    } while (0)

    int m0w = (wid & 1) * 64, n0w = (wid >> 1) * 32;
    int g = lid >> 3, r = lid & 7;
    uint32_t aBaseH = (uint32_t)((m0w + r + (g & 1)*8) * ASTRIDE + (g >> 1)*8);
    uint32_t bBaseH = (uint32_t)(STG_HALVES + (n0w + r + (g >> 1)*8) * ASTRIDE + (g & 1)*8);

    float acc[4][4][4];
    #pragma unroll
    for (int mi = 0; mi < 4; mi++)
        #pragma unroll
        for (int ni = 0; ni < 4; ni++)
            #pragma unroll
            for (int e = 0; e < 4; e++) acc[mi][ni][e] = 0.0f;

    #pragma unroll
    for (int s = 0; s < 3; s++) {
        LOADIT(s);
        asm volatile("cp.async.commit_group;");
    }

    for (int it = 0; it < KITERS; it++) {
        asm volatile("cp.async.wait_group 2;");
        __syncthreads();
        uint32_t sb = smb + (uint32_t)(it & 3) * STGB;
        #pragma unroll
        for (int ks = 0; ks < 32; ks += 16) {
            uint32_t b[4][2];
            #pragma unroll
            for (int np = 0; np < 2; np++) {
                uint32_t r0, r1, r2, r3;
                ldm_x4(r0, r1, r2, r3, sb + 2*(bBaseH + (uint32_t)(np*16*ASTRIDE) + ks));
                b[np*2][0] = r0;   b[np*2][1] = r1;
                b[np*2+1][0] = r2; b[np*2+1][1] = r3;
            }
            #pragma unroll
            for (int mi = 0; mi < 4; mi++) {
                uint32_t a[4];
                ldm_x4(a[0], a[1], a[2], a[3], sb + 2*(aBaseH + (uint32_t)(mi*16*ASTRIDE) + ks));
                #pragma unroll
                for (int ni = 0; ni < 4; ni++) mma16816(acc[mi][ni], a, b[ni]);
            }
        }
        int itn = it + 3;
        if (itn < KITERS) LOADIT(itn);
        asm volatile("cp.async.commit_group;");
    }

    int lr = lid >> 2, lc = (lid & 3) * 2;
    #pragma unroll
    for (int mi = 0; mi < 4; mi++) {
        #pragma unroll
        for (int ni = 0; ni < 4; ni++) {
            int row0 = mt*128 + m0w + mi*16 + lr;
            int col  = nt*128 + n0w + ni*8 + lc;
            float2 v0 = make_float2(acc[mi][ni][0], acc[mi][ni][1]);
            float2 v1 = make_float2(acc[mi][ni][2], acc[mi][ni][3]);
            if (Dd) {
                float2 d0 = *(const float2*)(Dd + (size_t)row0 * HID + col);
                float2 d1 = *(const float2*)(Dd + (size_t)(row0 + 8) * HID + col);
                v0.x += d0.x; v0.y += d0.y;
                v1.x += d1.x; v1.y += d1.y;
            }
            *(float2*)(C + (size_t)row0 * HID + col)       = v0;
            *(float2*)(C + (size_t)(row0 + 8) * HID + col) = v1;
        }
    }
    #undef LOADIT
}

// ---------------------------------------------------------------------------
// RoPE + scale + bf16 split of Q,K into head-major [bh][s][hi(128)|lo(128)]
// ---------------------------------------------------------------------------
__global__ __launch_bounds__(256) void rope_split_qk_kernel(
    const float* __restrict__ q, const float* __restrict__ k,
    bf16* __restrict__ q2g, bf16* __restrict__ k2g)
{
    int token = blockIdx.x;                  // b*SEQ + s
    int b = token >> 11, s = token & (SEQ-1);
    const float* qr = q + (size_t)token * HID;
    const float* kr = k + (size_t)token * HID;
    const float qs = 0.08838834764831845f;   // 1/sqrt(128)
    for (int idx = threadIdx.x; idx < NHEADS*64; idx += 256) {
        int h = idx >> 6, i = idx & 63;
        float c  = g_cos[s*64 + i];
        float sn = g_sin[s*64 + i];
        float q1 = qr[h*HDIM + i], q2v = qr[h*HDIM + i + 64];
        float k1 = kr[h*HDIM + i], k2v = kr[h*HDIM + i + 64];
        float qa = (q1*c - q2v*sn) * qs, qb = (q2v*c + q1*sn) * qs;
        float ka = k1*c - k2v*sn,        kb = k2v*c + k1*sn;
        bf16 h0,l0,h1,l1;
        bf16* qd = q2g + ((size_t)(b*NHEADS + h)*SEQ + s) * 256;
        bf16* kd = k2g + ((size_t)(b*NHEADS + h)*SEQ + s) * 256;
        bf16split(qa, h0, l0); bf16split(qb, h1, l1);
        qd[i] = h0; qd[i+64] = h1; qd[128+i] = l0; qd[128+i+64] = l1;
        bf16split(ka, h0, l0); bf16split(kb, h1, l1);
        kd[i] = h0; kd[i+64] = h1; kd[128+i] = l0; kd[128+i+64] = l1;
    }
}

// ---------------------------------------------------------------------------
// V transpose + split: v[b*s][h*128+d] -> vt[bh][d][s] hi, [d][SEQ+s] lo
// ---------------------------------------------------------------------------
__global__ __launch_bounds__(256) void vsplit_t_kernel(
    const float* __restrict__ v, bf16* __restrict__ vtg)
{
    __shared__ float t[32][33];
    int s0 = blockIdx.x * 32, d0 = blockIdx.y * 32, bh = blockIdx.z;
    int b = bh >> 4, h = bh & 15;
    int tx = threadIdx.x & 31, ty = threadIdx.x >> 5;
    #pragma unroll
    for (int i = 0; i < 4; i++)
        t[ty + 8*i][tx] = v[(size_t)(b*SEQ + s0 + ty + 8*i) * HID + h*HDIM + d0 + tx];
    __syncthreads();
    bf16* vb = vtg + (size_t)bh * HDIM * (2*SEQ);
    #pragma unroll
    for (int i = 0; i < 4; i++) {
        int d = d0 + ty + 8*i;
        float val = t[tx][ty + 8*i];
        bf16 hi, lo; bf16split(val, hi, lo);
        vb[(size_t)d*(2*SEQ) + s0 + tx]       = hi;
        vb[(size_t)d*(2*SEQ) + SEQ + s0 + tx] = lo;
    }
}

// ---------------------------------------------------------------------------
// HMMA flash attention. 256 thr / 8 warps, warp w owns q rows 16w..16w+15.
// Q tile (resident): [128][264] = [qh|ql]+pad.  K stages: [64][264] = [kh|kl].
// V stages: [128 d][136] = [vh(64 s)|vl(64 s)]+pad.  fp32 online softmax.
// ---------------------------------------------------------------------------
#define QS_STR 264
#define KS_STR 264
#define VS_STR 136
#define QS_OFF 0
#define KS_OFF (128*QS_STR)              // halves
#define KS_SZ  (64*KS_STR)
#define VS_OFF (KS_OFF + 2*KS_SZ)
#define VS_SZ  (128*VS_STR)
#define ATTN_SMEM ((VS_OFF + 2*VS_SZ)*2) // 204800 bytes

__global__ __launch_bounds__(256, 1) void attn_hmma_kernel(
    const bf16* __restrict__ q2g, const bf16* __restrict__ k2g,
    const bf16* __restrict__ vtg, float* __restrict__ ctx)
{
    extern __shared__ char smraw[];
    uint32_t smb = smem_u32(smraw);
    int tid = threadIdx.x, wid = tid >> 5, lid = tid & 31;
    int qt = blockIdx.x, hh = blockIdx.y, b = blockIdx.z;
    int bh = b*NHEADS + hh;
    const bf16* qbase = q2g + ((size_t)bh*SEQ + qt*128) * 256;
    const bf16* kbase = k2g + (size_t)bh*SEQ * 256;
    const bf16* vbase = vtg + (size_t)bh*HDIM*(2*SEQ);

    #define LOAD_KT(st_, s0_) do {                                              \
        _Pragma("unroll")                                                       \
        for (int i_ = 0; i_ < 8; i_++) {                                        \
            int idx_ = tid + 256*i_; int row_ = idx_ >> 5, seg_ = idx_ & 31;    \
            cpasync16(smb + 2*(KS_OFF + (st_)*KS_SZ + row_*KS_STR + seg_*8),    \
                      kbase + ((size_t)((s0_) + row_))*256 + seg_*8);           \
        } } while (0)
    #define LOAD_VT(st_, s0_) do {                                              \
        _Pragma("unroll")                                                       \
        for (int i_ = 0; i_ < 8; i_++) {                                        \
            int idx_ = tid + 256*i_;                                            \
            int pl_ = idx_ >> 10, dr_ = (idx_ >> 3) & 127, seg_ = idx_ & 7;     \
            cpasync16(smb + 2*(VS_OFF + (st_)*VS_SZ + dr_*VS_STR + pl_*64 + seg_*8), \
                      vbase + (size_t)dr_*(2*SEQ) + pl_*SEQ + (s0_) + seg_*8);  \
        } } while (0)

    // prologue: Q tile + stage 0 in group0; stage 1 in group1
    #pragma unroll
    for (int i = 0; i < 16; i++) {
        int idx = tid + 256*i; int row = idx >> 5, seg = idx & 31;
        cpasync16(smb + 2*(QS_OFF + row*QS_STR + seg*8),
                  qbase + (size_t)row*256 + seg*8);
    }
    LOAD_KT(0, 0); LOAD_VT(0, 0);
    asm volatile("cp.async.commit_group;");
    LOAD_KT(1, 64); LOAD_VT(1, 64);
    asm volatile("cp.async.commit_group;");

    int g = lid >> 3, r = lid & 7;
    uint32_t aQ = smb + 2*(QS_OFF + (uint32_t)((wid*16 + r + (g&1)*8)*QS_STR + (g>>1)*8));
    uint32_t bK = smb + 2*(KS_OFF + (uint32_t)((r + (g>>1)*8)*KS_STR + (g&1)*8));
    uint32_t bV = smb + 2*(VS_OFF + (uint32_t)((r + (g>>1)*8)*VS_STR + (g&1)*8));

    float oacc[16][4];
    #pragma unroll
    for (int n = 0; n < 16; n++)
        #pragma unroll
        for (int e = 0; e < 4; e++) oacc[n][e] = 0.0f;
    float m0 = -INFINITY, m1 = -INFINITY, l0 = 0.0f, l1 = 0.0f;

    for (int it = 0; it < SEQ/64; it++) {
        asm volatile("cp.async.wait_group 1;");
        __syncthreads();
        uint32_t kst = (uint32_t)((it & 1) * KS_SZ) * 2;
        uint32_t vst = (uint32_t)((it & 1) * VS_SZ) * 2;

        // ---- scores: S[16q x 64s] = Qh*Kh + Ql*Kh + Qh*Kl
        float sacc[8][4];
        #pragma unroll
        for (int n = 0; n < 8; n++)
            #pragma unroll
            for (int e = 0; e < 4; e++) sacc[n][e] = 0.0f;

        #pragma unroll
        for (int ks = 0; ks < 8; ks++) {
            uint32_t bfr[8][2];
            #pragma unroll
            for (int np = 0; np < 4; np++) {
                uint32_t r0,r1,r2,r3;
                ldm_x4(r0,r1,r2,r3, bK + kst + 2*(uint32_t)(np*16*KS_STR + ks*16));
                bfr[np*2][0]=r0; bfr[np*2][1]=r1; bfr[np*2+1][0]=r2; bfr[np*2+1][1]=r3;
            }
            uint32_t a[4];
            ldm_x4(a[0],a[1],a[2],a[3], aQ + 2*(uint32_t)(ks*16));          // Qh
            #pragma unroll
            for (int n = 0; n < 8; n++) mma16816(sacc[n], a, bfr[n]);
            ldm_x4(a[0],a[1],a[2],a[3], aQ + 2*(uint32_t)(128 + ks*16));    // Ql
            #pragma unroll
            for (int n = 0; n < 8; n++) mma16816(sacc[n], a, bfr[n]);
        }
        #pragma unroll
        for (int ks = 0; ks < 8; ks++) {                                     // Qh x Kl
            uint32_t bfr[8][2];
            #pragma unroll
            for (int np = 0; np < 4; np++) {
                uint32_t r0,r1,r2,r3;
                ldm_x4(r0,r1,r2,r3, bK + kst + 2*(uint32_t)(np*16*KS_STR + 128 + ks*16));
                bfr[np*2][0]=r0; bfr[np*2][1]=r1; bfr[np*2+1][0]=r2; bfr[np*2+1][1]=r3;
            }
            uint32_t a[4];
            ldm_x4(a[0],a[1],a[2],a[3], aQ + 2*(uint32_t)(ks*16));
            #pragma unroll
            for (int n = 0; n < 8; n++) mma16816(sacc[n], a, bfr[n]);
        }

        // ---- online softmax (warp-local; rows lid>>2 and lid>>2 + 8)
        float mt0 = -INFINITY, mt1 = -INFINITY;
        #pragma unroll
        for (int n = 0; n < 8; n++) {
            mt0 = fmaxf(mt0, fmaxf(sacc[n][0], sacc[n][1]));
            mt1 = fmaxf(mt1, fmaxf(sacc[n][2], sacc[n][3]));
        }
        mt0 = fmaxf(mt0, __shfl_xor_sync(0xffffffffu, mt0, 1));
        mt0 = fmaxf(mt0, __shfl_xor_sync(0xffffffffu, mt0, 2));
        mt1 = fmaxf(mt1, __shfl_xor_sync(0xffffffffu, mt1, 1));
        mt1 = fmaxf(mt1, __shfl_xor_sync(0xffffffffu, mt1, 2));
        float mn0 = fmaxf(m0, mt0), mn1 = fmaxf(m1, mt1);
        float al0 = __expf(m0 - mn0), al1 = __expf(m1 - mn1);
        m0 = mn0; m1 = mn1;

        uint32_t php0[8], php1[8], plp0[8], plp1[8];
        float rs0 = 0.0f, rs1 = 0.0f;
        #pragma unroll
        for (int n = 0; n < 8; n++) {
            float p0 = __expf(sacc[n][0] - mn0);
            float p1 = __expf(sacc[n][1] - mn0);
            float p2 = __expf(sacc[n][2] - mn1);
            float p3 = __expf(sacc[n][3] - mn1);
            rs0 += p0 + p1; rs1 += p2 + p3;
            php0[n] = packsplit_hi(p0, p1);  plp0[n] = packsplit_lo(p0, p1);
            php1[n] = packsplit_hi(p2, p3);  plp1[n] = packsplit_lo(p2, p3);
        }
        rs0 += __shfl_xor_sync(0xffffffffu, rs0, 1);
        rs0 += __shfl_xor_sync(0xffffffffu, rs0, 2);
        rs1 += __shfl_xor_sync(0xffffffffu, rs1, 1);
        rs1 += __shfl_xor_sync(0xffffffffu, rs1, 2);
        l0 = l0*al0 + rs0; l1 = l1*al1 + rs1;
        #pragma unroll
        for (int n = 0; n < 16; n++) {
            oacc[n][0] *= al0; oacc[n][1] *= al0;
            oacc[n][2] *= al1; oacc[n][3] *= al1;
        }

        // ---- O += Ph*Vh + Pl*Vh + Ph*Vl
        #pragma unroll
        for (int ks = 0; ks < 4; ks++) {
            uint32_t ahi[4] = { php0[2*ks], php1[2*ks], php0[2*ks+1], php1[2*ks+1] };
            uint32_t alo[4] = { plp0[2*ks], plp1[2*ks], plp0[2*ks+1], plp1[2*ks+1] };
            #pragma unroll
            for (int np = 0; np < 8; np++) {
                uint32_t r0,r1,r2,r3;
                ldm_x4(r0,r1,r2,r3, bV + vst + 2*(uint32_t)(np*16*VS_STR + ks*16));   // Vh
                uint32_t b0[2] = {r0, r1}, b1[2] = {r2, r3};
                mma16816(oacc[np*2],   ahi, b0); mma16816(oacc[np*2+1], ahi, b1);
                mma16816(oacc[np*2],   alo, b0); mma16816(oacc[np*2+1], alo, b1);
            }
            #pragma unroll
            for (int np = 0; np < 8; np++) {
                uint32_t r0,r1,r2,r3;
                ldm_x4(r0,r1,r2,r3, bV + vst + 2*(uint32_t)(np*16*VS_STR + 64 + ks*16)); // Vl
                uint32_t b0[2] = {r0, r1}, b1[2] = {r2, r3};
                mma16816(oacc[np*2],   ahi, b0); mma16816(oacc[np*2+1], ahi, b1);
            }
        }

        __syncthreads();
        int itn = it + 2;
        if (itn < SEQ/64) {
            LOAD_KT(itn & 1, itn*64); LOAD_VT(itn & 1, itn*64);
            asm volatile("cp.async.commit_group;");
        } else {
            asm volatile("cp.async.commit_group;");   // keep group count uniform
        }
    }

    // ---- epilogue
    float inv0 = 1.0f / l0, inv1 = 1.0f / l1;
    int row0 = qt*128 + wid*16 + (lid >> 2);
    int colb = 2*(lid & 3);
    float* cb = ctx + ((size_t)(b*SEQ) + row0) * HID + hh*HDIM;
    #pragma unroll
    for (int n = 0; n < 16; n++) {
        *(float2*)(cb + n*8 + colb) =
            make_float2(oacc[n][0]*inv0, oacc[n][1]*inv0);
        *(float2*)(cb + (size_t)8*HID + n*8 + colb) =
            make_float2(oacc[n][2]*inv1, oacc[n][3]*inv1);
    }
    #undef LOAD_KT
    #undef LOAD_VT
}

// ---------------------------------------------------------------------------
// silu(g1)*g3 fused with bf16 split -> out3 [R x 6144] = [hi | hi | lo]
// ---------------------------------------------------------------------------
__global__ __launch_bounds__(256) void silu_split_kernel(
    const float* __restrict__ g1, const float* __restrict__ g3, bf16* __restrict__ out3)
{
    int i = blockIdx.x * 256 + threadIdx.x;  // float4 index
    if (i >= MROWS * HID / 4) return;
    int row = i / (HID/4), col4 = i % (HID/4);
    float4 a = ((const float4*)g1)[i];
    float4 b = ((const float4*)g3)[i];
    float4 v;
    v.x = (a.x / (1.0f + expf(-a.x))) * b.x;
    v.y = (a.y / (1.0f + expf(-a.y))) * b.y;
    v.z = (a.z / (1.0f + expf(-a.z))) * b.z;
    v.w = (a.w / (1.0f + expf(-a.w))) * b.w;
    bf16 hx,lx,hy,ly,hz,lz,hw,lw;
    bf16split(v.x,hx,lx); bf16split(v.y,hy,ly); bf16split(v.z,hz,lz); bf16split(v.w,hw,lw);
    bf16* orow = out3 + (size_t)row * KTOT + col4*4;
    bf162 ha = {hx,hy}, hb = {hz,hw}, la = {lx,ly}, lb = {lz,lw};
    #define ST2(off, a_, b_) { bf162* p = (bf162*)&orow[off]; p[0] = a_; p[1] = b_; }
    ST2(0, ha, hb)  ST2(2048, ha, hb)  ST2(4096, la, lb)
    #undef ST2
}

// ---------------------------------------------------------------------------
// Launch
// ---------------------------------------------------------------------------
extern "C" void kernel_launch(void* const* d_in, const int* in_sizes, int n_in,
                              void* d_out, int out_size)
{
    (void)in_sizes; (void)n_in; (void)out_size;
    const float* hs  = (const float*)d_in[0];
    const float* Wq  = (const float*)d_in[1];
    const float* Wk  = (const float*)d_in[2];
    const float* Wv  = (const float*)d_in[3];
    const float* Wo  = (const float*)d_in[4];
    const float* w1  = (const float*)d_in[5];
    const float* w2  = (const float*)d_in[6];
    const float* w3  = (const float*)d_in[7];
    const float* ln1 = (const float*)d_in[8];
    const float* ln2 = (const float*)d_in[9];
    float* out = (float*)d_out;

    bf16 *xn3, *ctx3, *g13;
    bf16 *Wq3, *Wk3, *Wv3, *Wo3, *w13, *w23, *w33;
    bf16 *q2, *k2, *vt;
    float *q, *k, *v, *ctx, *h, *g1, *g3;
    cudaGetSymbolAddress((void**)&xn3,  g_xn3);
    cudaGetSymbolAddress((void**)&ctx3, g_ctx3);
    cudaGetSymbolAddress((void**)&g13,  g_g13);
    cudaGetSymbolAddress((void**)&Wq3,  g_Wq3);
    cudaGetSymbolAddress((void**)&Wk3,  g_Wk3);
    cudaGetSymbolAddress((void**)&Wv3,  g_Wv3);
    cudaGetSymbolAddress((void**)&Wo3,  g_Wo3);
    cudaGetSymbolAddress((void**)&w13,  g_w13);
    cudaGetSymbolAddress((void**)&w23,  g_w23);
    cudaGetSymbolAddress((void**)&w33,  g_w33);
    cudaGetSymbolAddress((void**)&q2,   g_q2);
    cudaGetSymbolAddress((void**)&k2,   g_k2);
    cudaGetSymbolAddress((void**)&vt,   g_vt);
    cudaGetSymbolAddress((void**)&q,    g_q);
    cudaGetSymbolAddress((void**)&k,    g_k);
    cudaGetSymbolAddress((void**)&v,    g_v);
    cudaGetSymbolAddress((void**)&ctx,  g_ctx);
    cudaGetSymbolAddress((void**)&h,    g_h);
    cudaGetSymbolAddress((void**)&g1,   g_g1);
    cudaGetSymbolAddress((void**)&g3,   g_g3);

    cudaFuncSetAttribute(attn_hmma_kernel, cudaFuncAttributeMaxDynamicSharedMemorySize, ATTN_SMEM);
    cudaFuncSetAttribute(hmma_gemm_kernel, cudaFuncAttributeMaxDynamicSharedMemorySize, GEMM_SMEM);

    dim3 gemm_grid(MROWS / 128, HID / 128);      // (32, 16)
    dim3 wgrid(HID / 32, HID / 32);              // (64, 64)
    int nv4 = MROWS * HID / 4;

    rope_table_kernel<<<(SEQ * 64 + 255) / 256, 256>>>();

    wsplit_kernel<<<wgrid, 256>>>(Wq, Wq3);
    wsplit_kernel<<<wgrid, 256>>>(Wk, Wk3);
    wsplit_kernel<<<wgrid, 256>>>(Wv, Wv3);
    wsplit_kernel<<<wgrid, 256>>>(Wo, Wo3);
    wsplit_kernel<<<wgrid, 256>>>(w1, w13);
    wsplit_kernel<<<wgrid, 256>>>(w2, w23);
    wsplit_kernel<<<wgrid, 256>>>(w3, w33);

    rmsnorm_split_kernel<<<MROWS, 256>>>(hs, ln1, xn3);

    hmma_gemm_kernel<<<gemm_grid, 256, GEMM_SMEM>>>(xn3, Wq3, nullptr, q);
    hmma_gemm_kernel<<<gemm_grid, 256, GEMM_SMEM>>>(xn3, Wk3, nullptr, k);
    hmma_gemm_kernel<<<gemm_grid, 256, GEMM_SMEM>>>(xn3, Wv3, nullptr, v);

    rope_split_qk_kernel<<<MROWS, 256>>>(q, k, q2, k2);
    vsplit_t_kernel<<<dim3(SEQ/32, HDIM/32, BATCH*NHEADS), 256>>>(v, vt);

    attn_hmma_kernel<<<dim3(SEQ/128, NHEADS, BATCH), 256, ATTN_SMEM>>>(q2, k2, vt, ctx);

    asplit_kernel<<<(nv4 + 255) / 256, 256>>>(ctx, ctx3);
    hmma_gemm_kernel<<<gemm_grid, 256, GEMM_SMEM>>>(ctx3, Wo3, hs, h);   // h = hs + ctx@Wo

    rmsnorm_split_kernel<<<MROWS, 256>>>(h, ln2, xn3);                   // reuse xn3 as y3

    hmma_gemm_kernel<<<gemm_grid, 256, GEMM_SMEM>>>(xn3, w13, nullptr, g1);
    hmma_gemm_kernel<<<gemm_grid, 256, GEMM_SMEM>>>(xn3, w33, nullptr, g3);

    silu_split_kernel<<<(nv4 + 255) / 256, 256>>>(g1, g3, g13);

    hmma_gemm_kernel<<<gemm_grid, 256, GEMM_SMEM>>>(g13, w23, h, out);   // out = h + mlp
}

// round 7
// speedup vs baseline: 4.2845x; 1.5541x over previous
#include <cuda_runtime.h>
#include <cuda_fp16.h>
#include <math.h>
#include <stdint.h>

// Problem constants
#define BATCH   2
#define SEQ     2048
#define HID     2048
#define NHEADS  16
#define HDIM    128
#define MROWS   (BATCH*SEQ)        // 4096
#define EPSV    1e-6f
#define KB2     (2*HID)            // 4096 fp16: B=[hi|lo], A=[A|A] (wrapped)

// ---------------------------------------------------------------------------
// Scratch (__device__ globals; no cudaMalloc allowed)
// ---------------------------------------------------------------------------
__device__ __half g_xh  [MROWS*HID];     // rmsnorm out (fp16 A operand)
__device__ __half g_ctxh[MROWS*HID];     // attention out (fp16 A operand)
__device__ __half g_g1h [MROWS*HID];     // silu out (fp16 A operand)
__device__ __half g_Wq2[HID*KB2];
__device__ __half g_Wk2[HID*KB2];
__device__ __half g_Wv2[HID*KB2];
__device__ __half g_Wo2[HID*KB2];
__device__ __half g_w12[HID*KB2];
__device__ __half g_w22[HID*KB2];
__device__ __half g_w32[HID*KB2];
__device__ float g_q  [MROWS*HID];
__device__ float g_k  [MROWS*HID];
__device__ float g_v  [MROWS*HID];
__device__ float g_h  [MROWS*HID];
__device__ float g_g1 [MROWS*HID];
__device__ float g_g3 [MROWS*HID];
__device__ float g_cos[SEQ*64];
__device__ float g_sin[SEQ*64];
// attention operands (fp16, head-major)
__device__ __half g_q2 [(size_t)BATCH*NHEADS*SEQ*HDIM];  // [bh][s][128]
__device__ __half g_k2 [(size_t)BATCH*NHEADS*SEQ*HDIM];  // [bh][s][128]
__device__ __half g_vt [(size_t)BATCH*NHEADS*HDIM*SEQ];  // [bh][d][s]

// ---------------------------------------------------------------------------
// Helpers
// ---------------------------------------------------------------------------
__device__ __forceinline__ uint32_t smem_u32(const void* p) {
    uint32_t a;
    asm("{ .reg .u64 t; cvta.to.shared.u64 t, %1; cvt.u32.u64 %0, t; }" : "=r"(a) : "l"(p));
    return a;
}
__device__ __forceinline__ void h16split(float x, __half& hi, __half& lo) {
    hi = __float2half_rn(x);
    lo = __float2half_rn(x - __half2float(hi));
}
__device__ __forceinline__ uint32_t packh(float x, float y) {
    __half2 t = __floats2half2_rn(x, y);
    return *(uint32_t*)&t;
}
__device__ __forceinline__ void cpasync16(uint32_t dst, const void* src) {
    asm volatile("cp.async.cg.shared.global [%0], [%1], 16;" :: "r"(dst), "l"(src));
}
__device__ __forceinline__ void ldm_x4(uint32_t& r0, uint32_t& r1, uint32_t& r2, uint32_t& r3,
                                       uint32_t addr) {
    asm volatile("ldmatrix.sync.aligned.m8n8.x4.shared.b16 {%0,%1,%2,%3}, [%4];"
                 : "=r"(r0), "=r"(r1), "=r"(r2), "=r"(r3) : "r"(addr));
}
__device__ __forceinline__ void mma16816h(float* c, const uint32_t* a, const uint32_t* b) {
    asm volatile(
        "mma.sync.aligned.m16n8k16.row.col.f32.f16.f16.f32 "
        "{%0,%1,%2,%3}, {%4,%5,%6,%7}, {%8,%9}, {%0,%1,%2,%3};"
        : "+f"(c[0]), "+f"(c[1]), "+f"(c[2]), "+f"(c[3])
        : "r"(a[0]), "r"(a[1]), "r"(a[2]), "r"(a[3]), "r"(b[0]), "r"(b[1]));
}

// ---------------------------------------------------------------------------
// RoPE cos/sin table
// ---------------------------------------------------------------------------
__global__ void rope_table_kernel() {
    int idx = blockIdx.x * 256 + threadIdx.x;
    if (idx < SEQ * 64) {
        int s = idx >> 6, i = idx & 63;
        double inv = pow(10000.0, -((double)(2 * i)) / 128.0);
        double ang = (double)s * inv;
        g_cos[idx] = (float)cos(ang);
        g_sin[idx] = (float)sin(ang);
    }
}

// ---------------------------------------------------------------------------
// RMSNorm -> fp16 (2048 wide)
// ---------------------------------------------------------------------------
__global__ __launch_bounds__(256) void rmsnorm_h_kernel(
    const float* __restrict__ x, const float* __restrict__ w, __half* __restrict__ outh)
{
    int row = blockIdx.x;
    const float4* xr = (const float4*)(x + (size_t)row * HID);
    float4 v0 = xr[threadIdx.x];
    float4 v1 = xr[threadIdx.x + 256];
    float ss = v0.x*v0.x + v0.y*v0.y + v0.z*v0.z + v0.w*v0.w
             + v1.x*v1.x + v1.y*v1.y + v1.z*v1.z + v1.w*v1.w;
    #pragma unroll
    for (int m = 16; m; m >>= 1) ss += __shfl_xor_sync(0xffffffffu, ss, m);
    __shared__ float red[8];
    if ((threadIdx.x & 31) == 0) red[threadIdx.x >> 5] = ss;
    __syncthreads();
    float tot = red[0] + red[1] + red[2] + red[3] + red[4] + red[5] + red[6] + red[7];
    float sc = rsqrtf(tot * (1.0f / (float)HID) + EPSV);
    const float4* wv = (const float4*)w;
    float4 w0 = wv[threadIdx.x];
    float4 w1v = wv[threadIdx.x + 256];
    __half* orow = outh + (size_t)row * HID;
    int c0 = threadIdx.x * 4, c1 = c0 + 1024;
    *(__half2*)&orow[c0]     = __floats2half2_rn(v0.x*sc*w0.x,  v0.y*sc*w0.y);
    *(__half2*)&orow[c0 + 2] = __floats2half2_rn(v0.z*sc*w0.z,  v0.w*sc*w0.w);
    *(__half2*)&orow[c1]     = __floats2half2_rn(v1.x*sc*w1v.x, v1.y*sc*w1v.y);
    *(__half2*)&orow[c1 + 2] = __floats2half2_rn(v1.z*sc*w1v.z, v1.w*sc*w1v.w);
}

// ---------------------------------------------------------------------------
// Weight transpose+split: W[K][N] f32 -> B2[N][4096] fp16 [hi | lo]
// ---------------------------------------------------------------------------
__global__ __launch_bounds__(256) void wsplit2_kernel(
    const float* __restrict__ W, __half* __restrict__ B2)
{
    __shared__ float t[32][33];
    int bn = blockIdx.x * 32;   // n-tile
    int bk = blockIdx.y * 32;   // k-tile
    int tx = threadIdx.x & 31, ty = threadIdx.x >> 5;  // 32 x 8
    #pragma unroll
    for (int i = 0; i < 4; i++)
        t[ty + 8*i][tx] = W[(size_t)(bk + ty + 8*i) * HID + bn + tx];
    __syncthreads();
    #pragma unroll
    for (int i = 0; i < 4; i++) {
        int n = bn + ty + 8*i;
        int k = bk + tx;
        float v = t[tx][ty + 8*i];
        __half hi, lo; h16split(v, hi, lo);
        __half* orow = B2 + (size_t)n * KB2;
        orow[k]        = hi;
        orow[k + 2048] = lo;
    }
}

// ---------------------------------------------------------------------------
// HMMA fp16 GEMM: C[4096 x 2048] = A[4096 x 2048] @ B2[2048 x 4096]^T (+Dd)
// 2-pass split: B2 = [B_hi | B_lo]; A chunk index wraps (it & 63).
// mma.sync.m16n8k16.f16 + ldmatrix + 4-stage cp.async. Tile 128x128, BK=32.
// ---------------------------------------------------------------------------
#define ASTRIDE 40
#define STG_HALVES (128*ASTRIDE)
#define STGB ((STG_HALVES*2)*2)
#define NSTG 4
#define GEMM_SMEM (NSTG*STGB)
#define KITERS (KB2/32)              // 128

__global__ __launch_bounds__(256, 2) void hmma_gemm_kernel(
    const __half* __restrict__ A, const __half* __restrict__ B2,
    const float* __restrict__ Dd, float* __restrict__ C)
{
    extern __shared__ char smraw[];
    uint32_t smb = smem_u32(smraw);
    int tid = threadIdx.x, wid = tid >> 5, lid = tid & 31;
    int mt = blockIdx.x, nt = blockIdx.y;

    int lrow0 = tid >> 2, lrow1 = lrow0 + 64;
    int seg = tid & 3;
    const __half* aptr0 = A + (size_t)(mt*128 + lrow0) * HID + seg*8;
    const __half* aptr1 = A + (size_t)(mt*128 + lrow1) * HID + seg*8;
    const __half* bptr0 = B2 + (size_t)(nt*128 + lrow0) * KB2 + seg*8;
    const __half* bptr1 = B2 + (size_t)(nt*128 + lrow1) * KB2 + seg*8;
    uint32_t aoff0 = (uint32_t)(lrow0*ASTRIDE + seg*8) * 2;
    uint32_t aoff1 = (uint32_t)(lrow1*ASTRIDE + seg*8) * 2;
    uint32_t boff0 = (uint32_t)(STG_HALVES + lrow0*ASTRIDE + seg*8) * 2;
    uint32_t boff1 = (uint32_t)(STG_HALVES + lrow1*ASTRIDE + seg*8) * 2;

    #define LOADIT(it_) do {                                            \
        uint32_t sb_ = smb + (uint32_t)((it_) & 3) * STGB;              \
        int k0a_ = ((it_) & 63) * 32;                                   \
        int k0b_ = (it_) * 32;                                          \
        cpasync16(sb_ + aoff0, aptr0 + k0a_);                           \
        cpasync16(sb_ + aoff1, aptr1 + k0a_);                           \
        cpasync16(sb_ + boff0, bptr0 + k0b_);                           \
        cpasync16(sb_ + boff1, bptr1 + k0b_);                           \
    } while (0)

    int m0w = (wid & 1) * 64, n0w = (wid >> 1) * 32;
    int g = lid >> 3, r = lid & 7;
    uint32_t aBaseH = (uint32_t)((m0w + r + (g & 1)*8) * ASTRIDE + (g >> 1)*8);
    uint32_t bBaseH = (uint32_t)(STG_HALVES + (n0w + r + (g >> 1)*8) * ASTRIDE + (g & 1)*8);

    float acc[4][4][4];
    #pragma unroll
    for (int mi = 0; mi < 4; mi++)
        #pragma unroll
        for (int ni = 0; ni < 4; ni++)
            #pragma unroll
            for (int e = 0; e < 4; e++) acc[mi][ni][e] = 0.0f;

    #pragma unroll
    for (int s = 0; s < 3; s++) {
        LOADIT(s);
        asm volatile("cp.async.commit_group;");
    }

    for (int it = 0; it < KITERS; it++) {
        asm volatile("cp.async.wait_group 2;");
        __syncthreads();
        uint32_t sb = smb + (uint32_t)(it & 3) * STGB;
        #pragma unroll
        for (int ks = 0; ks < 32; ks += 16) {
            uint32_t b[4][2];
            #pragma unroll
            for (int np = 0; np < 2; np++) {
                uint32_t r0, r1, r2, r3;
                ldm_x4(r0, r1, r2, r3, sb + 2*(bBaseH + (uint32_t)(np*16*ASTRIDE) + ks));
                b[np*2][0] = r0;   b[np*2][1] = r1;
                b[np*2+1][0] = r2; b[np*2+1][1] = r3;
            }
            #pragma unroll
            for (int mi = 0; mi < 4; mi++) {
                uint32_t a[4];
                ldm_x4(a[0], a[1], a[2], a[3], sb + 2*(aBaseH + (uint32_t)(mi*16*ASTRIDE) + ks));
                #pragma unroll
                for (int ni = 0; ni < 4; ni++) mma16816h(acc[mi][ni], a, b[ni]);
            }
        }
        int itn = it + 3;
        if (itn < KITERS) LOADIT(itn);
        asm volatile("cp.async.commit_group;");
    }

    int lr = lid >> 2, lc = (lid & 3) * 2;
    #pragma unroll
    for (int mi = 0; mi < 4; mi++) {
        #pragma unroll
        for (int ni = 0; ni < 4; ni++) {
            int row0 = mt*128 + m0w + mi*16 + lr;
            int col  = nt*128 + n0w + ni*8 + lc;
            float2 v0 = make_float2(acc[mi][ni][0], acc[mi][ni][1]);
            float2 v1 = make_float2(acc[mi][ni][2], acc[mi][ni][3]);
            if (Dd) {
                float2 d0 = *(const float2*)(Dd + (size_t)row0 * HID + col);
                float2 d1 = *(const float2*)(Dd + (size_t)(row0 + 8) * HID + col);
                v0.x += d0.x; v0.y += d0.y;
                v1.x += d1.x; v1.y += d1.y;
            }
            *(float2*)(C + (size_t)row0 * HID + col)       = v0;
            *(float2*)(C + (size_t)(row0 + 8) * HID + col) = v1;
        }
    }
    #undef LOADIT
}

// ---------------------------------------------------------------------------
// RoPE + scale -> fp16 Q,K head-major [bh][s][128]
// ---------------------------------------------------------------------------
__global__ __launch_bounds__(256) void rope_h_kernel(
    const float* __restrict__ q, const float* __restrict__ k,
    __half* __restrict__ q2g, __half* __restrict__ k2g)
{
    int token = blockIdx.x;                  // b*SEQ + s
    int b = token >> 11, s = token & (SEQ-1);
    const float* qr = q + (size_t)token * HID;
    const float* kr = k + (size_t)token * HID;
    const float qs = 0.08838834764831845f;   // 1/sqrt(128)
    for (int idx = threadIdx.x; idx < NHEADS*64; idx += 256) {
        int h = idx >> 6, i = idx & 63;
        float c  = g_cos[s*64 + i];
        float sn = g_sin[s*64 + i];
        float q1 = qr[h*HDIM + i], q2v = qr[h*HDIM + i + 64];
        float k1 = kr[h*HDIM + i], k2v = kr[h*HDIM + i + 64];
        __half* qd = q2g + ((size_t)(b*NHEADS + h)*SEQ + s) * HDIM;
        __half* kd = k2g + ((size_t)(b*NHEADS + h)*SEQ + s) * HDIM;
        qd[i]    = __float2half_rn((q1*c - q2v*sn) * qs);
        qd[i+64] = __float2half_rn((q2v*c + q1*sn) * qs);
        kd[i]    = __float2half_rn(k1*c - k2v*sn);
        kd[i+64] = __float2half_rn(k2v*c + k1*sn);
    }
}

// ---------------------------------------------------------------------------
// V transpose -> fp16 vt[bh][d][s]
// ---------------------------------------------------------------------------
__global__ __launch_bounds__(256) void vconv_kernel(
    const float* __restrict__ v, __half* __restrict__ vtg)
{
    __shared__ float t[32][33];
    int s0 = blockIdx.x * 32, d0 = blockIdx.y * 32, bh = blockIdx.z;
    int b = bh >> 4, h = bh & 15;
    int tx = threadIdx.x & 31, ty = threadIdx.x >> 5;
    #pragma unroll
    for (int i = 0; i < 4; i++)
        t[ty + 8*i][tx] = v[(size_t)(b*SEQ + s0 + ty + 8*i) * HID + h*HDIM + d0 + tx];
    __syncthreads();
    __half* vb = vtg + (size_t)bh * HDIM * SEQ;
    #pragma unroll
    for (int i = 0; i < 4; i++) {
        int d = d0 + ty + 8*i;
        vb[(size_t)d*SEQ + s0 + tx] = __float2half_rn(t[tx][ty + 8*i]);
    }
}

// ---------------------------------------------------------------------------
// HMMA flash attention, single-pass fp16. 8 warps; warp w owns q rows 16w..16w+15.
// Q resident [128][136]; K stages [64][136]; V stages [128 d][72]; fp32 softmax.
// Epilogue writes ctx directly as fp16 [b*s][h*128+d].
// ---------------------------------------------------------------------------
#define QS_STR 136
#define KS_STR 136
#define VS_STR 72
#define QS_OFF 0
#define KS_OFF (128*QS_STR)              // halves
#define KS_SZ  (64*KS_STR)
#define VS_OFF (KS_OFF + 2*KS_SZ)
#define VS_SZ  (128*VS_STR)
#define ATTN_SMEM ((VS_OFF + 2*VS_SZ)*2) // 106496 bytes

__global__ __launch_bounds__(256, 1) void attn_hmma_kernel(
    const __half* __restrict__ q2g, const __half* __restrict__ k2g,
    const __half* __restrict__ vtg, __half* __restrict__ ctxh)
{
    extern __shared__ char smraw[];
    uint32_t smb = smem_u32(smraw);
    int tid = threadIdx.x, wid = tid >> 5, lid = tid & 31;
    int qt = blockIdx.x, hh = blockIdx.y, b = blockIdx.z;
    int bh = b*NHEADS + hh;
    const __half* qbase = q2g + ((size_t)bh*SEQ + qt*128) * HDIM;
    const __half* kbase = k2g + (size_t)bh*SEQ * HDIM;
    const __half* vbase = vtg + (size_t)bh*HDIM*SEQ;

    #define LOAD_KT(st_, s0_) do {                                              \
        _Pragma("unroll")                                                       \
        for (int i_ = 0; i_ < 4; i_++) {                                        \
            int idx_ = tid + 256*i_; int row_ = idx_ >> 4, seg_ = idx_ & 15;    \
            cpasync16(smb + 2*(KS_OFF + (st_)*KS_SZ + row_*KS_STR + seg_*8),    \
                      kbase + ((size_t)((s0_) + row_))*HDIM + seg_*8);          \
        } } while (0)
    #define LOAD_VT(st_, s0_) do {                                              \
        _Pragma("unroll")                                                       \
        for (int i_ = 0; i_ < 4; i_++) {                                        \
            int idx_ = tid + 256*i_; int dr_ = idx_ >> 3, seg_ = idx_ & 7;      \
            cpasync16(smb + 2*(VS_OFF + (st_)*VS_SZ + dr_*VS_STR + seg_*8),     \
                      vbase + (size_t)dr_*SEQ + (s0_) + seg_*8);                \
        } } while (0)

    // prologue: Q tile + stage 0 in group0; stage 1 in group1
    #pragma unroll
    for (int i = 0; i < 8; i++) {
        int idx = tid + 256*i; int row = idx >> 4, seg = idx & 15;
        cpasync16(smb + 2*(QS_OFF + row*QS_STR + seg*8),
                  qbase + (size_t)row*HDIM + seg*8);
    }
    LOAD_KT(0, 0); LOAD_VT(0, 0);
    asm volatile("cp.async.commit_group;");
    LOAD_KT(1, 64); LOAD_VT(1, 64);
    asm volatile("cp.async.commit_group;");

    int g = lid >> 3, r = lid & 7;
    uint32_t aQ = smb + 2*(QS_OFF + (uint32_t)((wid*16 + r + (g&1)*8)*QS_STR + (g>>1)*8));
    uint32_t bK = smb + 2*(KS_OFF + (uint32_t)((r + (g>>1)*8)*KS_STR + (g&1)*8));
    uint32_t bV = smb + 2*(VS_OFF + (uint32_t)((r + (g>>1)*8)*VS_STR + (g&1)*8));

    float oacc[16][4];
    #pragma unroll
    for (int n = 0; n < 16; n++)
        #pragma unroll
        for (int e = 0; e < 4; e++) oacc[n][e] = 0.0f;
    float m0 = -INFINITY, m1 = -INFINITY, l0 = 0.0f, l1 = 0.0f;

    for (int it = 0; it < SEQ/64; it++) {
        asm volatile("cp.async.wait_group 1;");
        __syncthreads();
        uint32_t kst = (uint32_t)((it & 1) * KS_SZ) * 2;
        uint32_t vst = (uint32_t)((it & 1) * VS_SZ) * 2;

        // ---- scores: S[16q x 64s] = Q K^T (single fp16 pass)
        float sacc[8][4];
        #pragma unroll
        for (int n = 0; n < 8; n++)
            #pragma unroll
            for (int e = 0; e < 4; e++) sacc[n][e] = 0.0f;

        #pragma unroll
        for (int ks = 0; ks < 8; ks++) {
            uint32_t bfr[8][2];
            #pragma unroll
            for (int np = 0; np < 4; np++) {
                uint32_t r0,r1,r2,r3;
                ldm_x4(r0,r1,r2,r3, bK + kst + 2*(uint32_t)(np*16*KS_STR + ks*16));
                bfr[np*2][0]=r0; bfr[np*2][1]=r1; bfr[np*2+1][0]=r2; bfr[np*2+1][1]=r3;
            }
            uint32_t a[4];
            ldm_x4(a[0],a[1],a[2],a[3], aQ + 2*(uint32_t)(ks*16));
            #pragma unroll
            for (int n = 0; n < 8; n++) mma16816h(sacc[n], a, bfr[n]);
        }

        // ---- online softmax (warp-local; rows lid>>2 and lid>>2 + 8)
        float mt0 = -INFINITY, mt1 = -INFINITY;
        #pragma unroll
        for (int n = 0; n < 8; n++) {
            mt0 = fmaxf(mt0, fmaxf(sacc[n][0], sacc[n][1]));
            mt1 = fmaxf(mt1, fmaxf(sacc[n][2], sacc[n][3]));
        }
        mt0 = fmaxf(mt0, __shfl_xor_sync(0xffffffffu, mt0, 1));
        mt0 = fmaxf(mt0, __shfl_xor_sync(0xffffffffu, mt0, 2));
        mt1 = fmaxf(mt1, __shfl_xor_sync(0xffffffffu, mt1, 1));
        mt1 = fmaxf(mt1, __shfl_xor_sync(0xffffffffu, mt1, 2));
        float mn0 = fmaxf(m0, mt0), mn1 = fmaxf(m1, mt1);
        float al0 = __expf(m0 - mn0), al1 = __expf(m1 - mn1);
        m0 = mn0; m1 = mn1;

        uint32_t ph0[8], ph1[8];
        float rs0 = 0.0f, rs1 = 0.0f;
        #pragma unroll
        for (int n = 0; n < 8; n++) {
            float p0 = __expf(sacc[n][0] - mn0);
            float p1 = __expf(sacc[n][1] - mn0);
            float p2 = __expf(sacc[n][2] - mn1);
            float p3 = __expf(sacc[n][3] - mn1);
            rs0 += p0 + p1; rs1 += p2 + p3;
            ph0[n] = packh(p0, p1);
            ph1[n] = packh(p2, p3);
        }
        rs0 += __shfl_xor_sync(0xffffffffu, rs0, 1);
        rs0 += __shfl_xor_sync(0xffffffffu, rs0, 2);
        rs1 += __shfl_xor_sync(0xffffffffu, rs1, 1);
        rs1 += __shfl_xor_sync(0xffffffffu, rs1, 2);
        l0 = l0*al0 + rs0; l1 = l1*al1 + rs1;
        #pragma unroll
        for (int n = 0; n < 16; n++) {
            oacc[n][0] *= al0; oacc[n][1] *= al0;
            oacc[n][2] *= al1; oacc[n][3] *= al1;
        }

        // ---- O += P V (single fp16 pass)
        #pragma unroll
        for (int ks = 0; ks < 4; ks++) {
            uint32_t a[4] = { ph0[2*ks], ph1[2*ks], ph0[2*ks+1], ph1[2*ks+1] };
            #pragma unroll
            for (int np = 0; np < 8; np++) {
                uint32_t r0,r1,r2,r3;
                ldm_x4(r0,r1,r2,r3, bV + vst + 2*(uint32_t)(np*16*VS_STR + ks*16));
                uint32_t b0[2] = {r0, r1}, b1[2] = {r2, r3};
                mma16816h(oacc[np*2], a, b0); mma16816h(oacc[np*2+1], a, b1);
            }
        }

        __syncthreads();
        int itn = it + 2;
        if (itn < SEQ/64) {
            LOAD_KT(itn & 1, itn*64); LOAD_VT(itn & 1, itn*64);
        }
        asm volatile("cp.async.commit_group;");
    }

    // ---- epilogue: write fp16 ctx
    float inv0 = 1.0f / l0, inv1 = 1.0f / l1;
    int row0 = qt*128 + wid*16 + (lid >> 2);
    int colb = 2*(lid & 3);
    __half* cb = ctxh + ((size_t)(b*SEQ) + row0) * HID + hh*HDIM;
    #pragma unroll
    for (int n = 0; n < 16; n++) {
        *(__half2*)(cb + n*8 + colb) =
            __floats2half2_rn(oacc[n][0]*inv0, oacc[n][1]*inv0);
        *(__half2*)(cb + (size_t)8*HID + n*8 + colb) =
            __floats2half2_rn(oacc[n][2]*inv1, oacc[n][3]*inv1);
    }
    #undef LOAD_KT
    #undef LOAD_VT
}

// ---------------------------------------------------------------------------
// silu(g1)*g3 -> fp16 (2048 wide)
// ---------------------------------------------------------------------------
__global__ __launch_bounds__(256) void silu_h_kernel(
    const float* __restrict__ g1, const float* __restrict__ g3, __half* __restrict__ outh)
{
    int i = blockIdx.x * 256 + threadIdx.x;  // float4 index
    if (i >= MROWS * HID / 4) return;
    float4 a = ((const float4*)g1)[i];
    float4 b = ((const float4*)g3)[i];
    float vx = (a.x / (1.0f + expf(-a.x))) * b.x;
    float vy = (a.y / (1.0f + expf(-a.y))) * b.y;
    float vz = (a.z / (1.0f + expf(-a.z))) * b.z;
    float vw = (a.w / (1.0f + expf(-a.w))) * b.w;
    __half2* o = (__half2*)(outh + (size_t)i * 4);
    o[0] = __floats2half2_rn(vx, vy);
    o[1] = __floats2half2_rn(vz, vw);
}

// ---------------------------------------------------------------------------
// Launch
// ---------------------------------------------------------------------------
extern "C" void kernel_launch(void* const* d_in, const int* in_sizes, int n_in,
                              void* d_out, int out_size)
{
    (void)in_sizes; (void)n_in; (void)out_size;
    const float* hs  = (const float*)d_in[0];
    const float* Wq  = (const float*)d_in[1];
    const float* Wk  = (const float*)d_in[2];
    const float* Wv  = (const float*)d_in[3];
    const float* Wo  = (const float*)d_in[4];
    const float* w1  = (const float*)d_in[5];
    const float* w2  = (const float*)d_in[6];
    const float* w3  = (const float*)d_in[7];
    const float* ln1 = (const float*)d_in[8];
    const float* ln2 = (const float*)d_in[9];
    float* out = (float*)d_out;

    __half *xh, *ctxh, *g1h;
    __half *Wq2, *Wk2, *Wv2, *Wo2, *w12, *w22, *w32;
    __half *q2, *k2, *vt;
    float *q, *k, *v, *h, *g1, *g3;
    cudaGetSymbolAddress((void**)&xh,   g_xh);
    cudaGetSymbolAddress((void**)&ctxh, g_ctxh);
    cudaGetSymbolAddress((void**)&g1h,  g_g1h);
    cudaGetSymbolAddress((void**)&Wq2,  g_Wq2);
    cudaGetSymbolAddress((void**)&Wk2,  g_Wk2);
    cudaGetSymbolAddress((void**)&Wv2,  g_Wv2);
    cudaGetSymbolAddress((void**)&Wo2,  g_Wo2);
    cudaGetSymbolAddress((void**)&w12,  g_w12);
    cudaGetSymbolAddress((void**)&w22,  g_w22);
    cudaGetSymbolAddress((void**)&w32,  g_w32);
    cudaGetSymbolAddress((void**)&q2,   g_q2);
    cudaGetSymbolAddress((void**)&k2,   g_k2);
    cudaGetSymbolAddress((void**)&vt,   g_vt);
    cudaGetSymbolAddress((void**)&q,    g_q);
    cudaGetSymbolAddress((void**)&k,    g_k);
    cudaGetSymbolAddress((void**)&v,    g_v);
    cudaGetSymbolAddress((void**)&h,    g_h);
    cudaGetSymbolAddress((void**)&g1,   g_g1);
    cudaGetSymbolAddress((void**)&g3,   g_g3);

    cudaFuncSetAttribute(attn_hmma_kernel, cudaFuncAttributeMaxDynamicSharedMemorySize, ATTN_SMEM);
    cudaFuncSetAttribute(hmma_gemm_kernel, cudaFuncAttributeMaxDynamicSharedMemorySize, GEMM_SMEM);

    dim3 gemm_grid(MROWS / 128, HID / 128);      // (32, 16)
    dim3 wgrid(HID / 32, HID / 32);              // (64, 64)
    int nv4 = MROWS * HID / 4;

    rope_table_kernel<<<(SEQ * 64 + 255) / 256, 256>>>();

    wsplit2_kernel<<<wgrid, 256>>>(Wq, Wq2);
    wsplit2_kernel<<<wgrid, 256>>>(Wk, Wk2);
    wsplit2_kernel<<<wgrid, 256>>>(Wv, Wv2);
    wsplit2_kernel<<<wgrid, 256>>>(Wo, Wo2);
    wsplit2_kernel<<<wgrid, 256>>>(w1, w12);
    wsplit2_kernel<<<wgrid, 256>>>(w2, w22);
    wsplit2_kernel<<<wgrid, 256>>>(w3, w32);

    rmsnorm_h_kernel<<<MROWS, 256>>>(hs, ln1, xh);

    hmma_gemm_kernel<<<gemm_grid, 256, GEMM_SMEM>>>(xh, Wq2, nullptr, q);
    hmma_gemm_kernel<<<gemm_grid, 256, GEMM_SMEM>>>(xh, Wk2, nullptr, k);
    hmma_gemm_kernel<<<gemm_grid, 256, GEMM_SMEM>>>(xh, Wv2, nullptr, v);

    rope_h_kernel<<<MROWS, 256>>>(q, k, q2, k2);
    vconv_kernel<<<dim3(SEQ/32, HDIM/32, BATCH*NHEADS), 256>>>(v, vt);

    attn_hmma_kernel<<<dim3(SEQ/128, NHEADS, BATCH), 256, ATTN_SMEM>>>(q2, k2, vt, ctxh);

    hmma_gemm_kernel<<<gemm_grid, 256, GEMM_SMEM>>>(ctxh, Wo2, hs, h);   // h = hs + ctx@Wo

    rmsnorm_h_kernel<<<MROWS, 256>>>(h, ln2, xh);                        // reuse xh as y

    hmma_gemm_kernel<<<gemm_grid, 256, GEMM_SMEM>>>(xh, w12, nullptr, g1);
    hmma_gemm_kernel<<<gemm_grid, 256, GEMM_SMEM>>>(xh, w32, nullptr, g3);

    silu_h_kernel<<<(nv4 + 255) / 256, 256>>>(g1, g3, g1h);

    hmma_gemm_kernel<<<gemm_grid, 256, GEMM_SMEM>>>(g1h, w22, h, out);   // out = h + mlp
}

// round 8
// speedup vs baseline: 7.0037x; 1.6346x over previous
#include <cuda_runtime.h>
#include <cuda_fp16.h>
#include <math.h>
#include <stdint.h>

// Problem constants
#define BATCH   2
#define SEQ     2048
#define HID     2048
#define NHEADS  16
#define HDIM    128
#define MROWS   (BATCH*SEQ)        // 4096
#define EPSV    1e-6f

// ---------------------------------------------------------------------------
// Scratch (__device__ globals; no cudaMalloc allowed)
// ---------------------------------------------------------------------------
__device__ __half g_xh  [MROWS*HID];     // rmsnorm out (fp16 A operand)
__device__ __half g_ctxh[MROWS*HID];     // attention out (fp16 A operand)
__device__ __half g_g1h [MROWS*HID];     // silu out (fp16 A operand)
__device__ __half g_Wq2[HID*HID];        // transposed fp16 weights [N][K]
__device__ __half g_Wk2[HID*HID];
__device__ __half g_Wv2[HID*HID];
__device__ __half g_Wo2[HID*HID];
__device__ __half g_w12[HID*HID];
__device__ __half g_w22[HID*HID];
__device__ __half g_w32[HID*HID];
__device__ float g_q  [MROWS*HID];
__device__ float g_k  [MROWS*HID];
__device__ float g_v  [MROWS*HID];
__device__ float g_h  [MROWS*HID];
__device__ float g_g1 [MROWS*HID];
__device__ float g_g3 [MROWS*HID];
__device__ float g_cos[SEQ*64];
__device__ float g_sin[SEQ*64];
// attention operands (fp16, head-major)
__device__ __half g_q2 [(size_t)BATCH*NHEADS*SEQ*HDIM];  // [bh][s][128]
__device__ __half g_k2 [(size_t)BATCH*NHEADS*SEQ*HDIM];  // [bh][s][128]
__device__ __half g_vt [(size_t)BATCH*NHEADS*HDIM*SEQ];  // [bh][d][s]

// ---------------------------------------------------------------------------
// Helpers
// ---------------------------------------------------------------------------
__device__ __forceinline__ uint32_t smem_u32(const void* p) {
    uint32_t a;
    asm("{ .reg .u64 t; cvta.to.shared.u64 t, %1; cvt.u32.u64 %0, t; }" : "=r"(a) : "l"(p));
    return a;
}
__device__ __forceinline__ uint32_t packh(float x, float y) {
    __half2 t = __floats2half2_rn(x, y);
    return *(uint32_t*)&t;
}
__device__ __forceinline__ void cpasync16(uint32_t dst, const void* src) {
    asm volatile("cp.async.cg.shared.global [%0], [%1], 16;" :: "r"(dst), "l"(src));
}
__device__ __forceinline__ void ldm_x4(uint32_t& r0, uint32_t& r1, uint32_t& r2, uint32_t& r3,
                                       uint32_t addr) {
    asm volatile("ldmatrix.sync.aligned.m8n8.x4.shared.b16 {%0,%1,%2,%3}, [%4];"
                 : "=r"(r0), "=r"(r1), "=r"(r2), "=r"(r3) : "r"(addr));
}
__device__ __forceinline__ void mma16816h(float* c, const uint32_t* a, const uint32_t* b) {
    asm volatile(
        "mma.sync.aligned.m16n8k16.row.col.f32.f16.f16.f32 "
        "{%0,%1,%2,%3}, {%4,%5,%6,%7}, {%8,%9}, {%0,%1,%2,%3};"
        : "+f"(c[0]), "+f"(c[1]), "+f"(c[2]), "+f"(c[3])
        : "r"(a[0]), "r"(a[1]), "r"(a[2]), "r"(a[3]), "r"(b[0]), "r"(b[1]));
}

// ---------------------------------------------------------------------------
// RoPE cos/sin table
// ---------------------------------------------------------------------------
__global__ void rope_table_kernel() {
    int idx = blockIdx.x * 256 + threadIdx.x;
    if (idx < SEQ * 64) {
        int s = idx >> 6, i = idx & 63;
        double inv = pow(10000.0, -((double)(2 * i)) / 128.0);
        double ang = (double)s * inv;
        g_cos[idx] = (float)cos(ang);
        g_sin[idx] = (float)sin(ang);
    }
}

// ---------------------------------------------------------------------------
// RMSNorm -> fp16 (2048 wide)
// ---------------------------------------------------------------------------
__global__ __launch_bounds__(256) void rmsnorm_h_kernel(
    const float* __restrict__ x, const float* __restrict__ w, __half* __restrict__ outh)
{
    int row = blockIdx.x;
    const float4* xr = (const float4*)(x + (size_t)row * HID);
    float4 v0 = xr[threadIdx.x];
    float4 v1 = xr[threadIdx.x + 256];
    float ss = v0.x*v0.x + v0.y*v0.y + v0.z*v0.z + v0.w*v0.w
             + v1.x*v1.x + v1.y*v1.y + v1.z*v1.z + v1.w*v1.w;
    #pragma unroll
    for (int m = 16; m; m >>= 1) ss += __shfl_xor_sync(0xffffffffu, ss, m);
    __shared__ float red[8];
    if ((threadIdx.x & 31) == 0) red[threadIdx.x >> 5] = ss;
    __syncthreads();
    float tot = red[0] + red[1] + red[2] + red[3] + red[4] + red[5] + red[6] + red[7];
    float sc = rsqrtf(tot * (1.0f / (float)HID) + EPSV);
    const float4* wv = (const float4*)w;
    float4 w0 = wv[threadIdx.x];
    float4 w1v = wv[threadIdx.x + 256];
    __half* orow = outh + (size_t)row * HID;
    int c0 = threadIdx.x * 4, c1 = c0 + 1024;
    *(__half2*)&orow[c0]     = __floats2half2_rn(v0.x*sc*w0.x,  v0.y*sc*w0.y);
    *(__half2*)&orow[c0 + 2] = __floats2half2_rn(v0.z*sc*w0.z,  v0.w*sc*w0.w);
    *(__half2*)&orow[c1]     = __floats2half2_rn(v1.x*sc*w1v.x, v1.y*sc*w1v.y);
    *(__half2*)&orow[c1 + 2] = __floats2half2_rn(v1.z*sc*w1v.z, v1.w*sc*w1v.w);
}

// ---------------------------------------------------------------------------
// Weight transpose: W[K][N] f32 -> B[N][2048] fp16
// ---------------------------------------------------------------------------
__global__ __launch_bounds__(256) void wtrans_kernel(
    const float* __restrict__ W, __half* __restrict__ B)
{
    __shared__ float t[32][33];
    int bn = blockIdx.x * 32;   // n-tile
    int bk = blockIdx.y * 32;   // k-tile
    int tx = threadIdx.x & 31, ty = threadIdx.x >> 5;  // 32 x 8
    #pragma unroll
    for (int i = 0; i < 4; i++)
        t[ty + 8*i][tx] = W[(size_t)(bk + ty + 8*i) * HID + bn + tx];
    __syncthreads();
    #pragma unroll
    for (int i = 0; i < 4; i++) {
        int n = bn + ty + 8*i;
        int k = bk + tx;
        B[(size_t)n * HID + k] = __float2half_rn(t[tx][ty + 8*i]);
    }
}

// ---------------------------------------------------------------------------
// HMMA fp16 GEMM: C[4096 x 2048] = A[4096 x 2048] @ B[2048 x 2048]^T (+Dd)
// mma.sync.m16n8k16.f16 + ldmatrix + 4-stage cp.async. Tile 128x128, BK=32.
// ---------------------------------------------------------------------------
#define ASTRIDE 40
#define STG_HALVES (128*ASTRIDE)
#define STGB ((STG_HALVES*2)*2)
#define NSTG 4
#define GEMM_SMEM (NSTG*STGB)
#define KITERS (HID/32)              // 64

__global__ __launch_bounds__(256, 2) void hmma_gemm_kernel(
    const __half* __restrict__ A, const __half* __restrict__ B,
    const float* __restrict__ Dd, float* __restrict__ C)
{
    extern __shared__ char smraw[];
    uint32_t smb = smem_u32(smraw);
    int tid = threadIdx.x, wid = tid >> 5, lid = tid & 31;
    int mt = blockIdx.x, nt = blockIdx.y;

    int lrow0 = tid >> 2, lrow1 = lrow0 + 64;
    int seg = tid & 3;
    const __half* aptr0 = A + (size_t)(mt*128 + lrow0) * HID + seg*8;
    const __half* aptr1 = A + (size_t)(mt*128 + lrow1) * HID + seg*8;
    const __half* bptr0 = B + (size_t)(nt*128 + lrow0) * HID + seg*8;
    const __half* bptr1 = B + (size_t)(nt*128 + lrow1) * HID + seg*8;
    uint32_t aoff0 = (uint32_t)(lrow0*ASTRIDE + seg*8) * 2;
    uint32_t aoff1 = (uint32_t)(lrow1*ASTRIDE + seg*8) * 2;
    uint32_t boff0 = (uint32_t)(STG_HALVES + lrow0*ASTRIDE + seg*8) * 2;
    uint32_t boff1 = (uint32_t)(STG_HALVES + lrow1*ASTRIDE + seg*8) * 2;

    #define LOADIT(it_) do {                                            \
        uint32_t sb_ = smb + (uint32_t)((it_) & 3) * STGB;              \
        int k0_ = (it_) * 32;                                           \
        cpasync16(sb_ + aoff0, aptr0 + k0_);                            \
        cpasync16(sb_ + aoff1, aptr1 + k0_);                            \
        cpasync16(sb_ + boff0, bptr0 + k0_);                            \
        cpasync16(sb_ + boff1, bptr1 + k0_);                            \
    } while (0)

    int m0w = (wid & 1) * 64, n0w = (wid >> 1) * 32;
    int g = lid >> 3, r = lid & 7;
    uint32_t aBaseH = (uint32_t)((m0w + r + (g & 1)*8) * ASTRIDE + (g >> 1)*8);
    uint32_t bBaseH = (uint32_t)(STG_HALVES + (n0w + r + (g >> 1)*8) * ASTRIDE + (g & 1)*8);

    float acc[4][4][4];
    #pragma unroll
    for (int mi = 0; mi < 4; mi++)
        #pragma unroll
        for (int ni = 0; ni < 4; ni++)
            #pragma unroll
            for (int e = 0; e < 4; e++) acc[mi][ni][e] = 0.0f;

    #pragma unroll
    for (int s = 0; s < 3; s++) {
        LOADIT(s);
        asm volatile("cp.async.commit_group;");
    }

    for (int it = 0; it < KITERS; it++) {
        asm volatile("cp.async.wait_group 2;");
        __syncthreads();
        uint32_t sb = smb + (uint32_t)(it & 3) * STGB;
        #pragma unroll
        for (int ks = 0; ks < 32; ks += 16) {
            uint32_t b[4][2];
            #pragma unroll
            for (int np = 0; np < 2; np++) {
                uint32_t r0, r1, r2, r3;
                ldm_x4(r0, r1, r2, r3, sb + 2*(bBaseH + (uint32_t)(np*16*ASTRIDE) + ks));
                b[np*2][0] = r0;   b[np*2][1] = r1;
                b[np*2+1][0] = r2; b[np*2+1][1] = r3;
            }
            #pragma unroll
            for (int mi = 0; mi < 4; mi++) {
                uint32_t a[4];
                ldm_x4(a[0], a[1], a[2], a[3], sb + 2*(aBaseH + (uint32_t)(mi*16*ASTRIDE) + ks));
                #pragma unroll
                for (int ni = 0; ni < 4; ni++) mma16816h(acc[mi][ni], a, b[ni]);
            }
        }
        int itn = it + 3;
        if (itn < KITERS) LOADIT(itn);
        asm volatile("cp.async.commit_group;");
    }

    int lr = lid >> 2, lc = (lid & 3) * 2;
    #pragma unroll
    for (int mi = 0; mi < 4; mi++) {
        #pragma unroll
        for (int ni = 0; ni < 4; ni++) {
            int row0 = mt*128 + m0w + mi*16 + lr;
            int col  = nt*128 + n0w + ni*8 + lc;
            float2 v0 = make_float2(acc[mi][ni][0], acc[mi][ni][1]);
            float2 v1 = make_float2(acc[mi][ni][2], acc[mi][ni][3]);
            if (Dd) {
                float2 d0 = *(const float2*)(Dd + (size_t)row0 * HID + col);
                float2 d1 = *(const float2*)(Dd + (size_t)(row0 + 8) * HID + col);
                v0.x += d0.x; v0.y += d0.y;
                v1.x += d1.x; v1.y += d1.y;
            }
            *(float2*)(C + (size_t)row0 * HID + col)       = v0;
            *(float2*)(C + (size_t)(row0 + 8) * HID + col) = v1;
        }
    }
    #undef LOADIT
}

// ---------------------------------------------------------------------------
// RoPE + scale -> fp16 Q,K head-major [bh][s][128]
// ---------------------------------------------------------------------------
__global__ __launch_bounds__(256) void rope_h_kernel(
    const float* __restrict__ q, const float* __restrict__ k,
    __half* __restrict__ q2g, __half* __restrict__ k2g)
{
    int token = blockIdx.x;                  // b*SEQ + s
    int b = token >> 11, s = token & (SEQ-1);
    const float* qr = q + (size_t)token * HID;
    const float* kr = k + (size_t)token * HID;
    const float qs = 0.08838834764831845f;   // 1/sqrt(128)
    for (int idx = threadIdx.x; idx < NHEADS*64; idx += 256) {
        int h = idx >> 6, i = idx & 63;
        float c  = g_cos[s*64 + i];
        float sn = g_sin[s*64 + i];
        float q1 = qr[h*HDIM + i], q2v = qr[h*HDIM + i + 64];
        float k1 = kr[h*HDIM + i], k2v = kr[h*HDIM + i + 64];
        __half* qd = q2g + ((size_t)(b*NHEADS + h)*SEQ + s) * HDIM;
        __half* kd = k2g + ((size_t)(b*NHEADS + h)*SEQ + s) * HDIM;
        qd[i]    = __float2half_rn((q1*c - q2v*sn) * qs);
        qd[i+64] = __float2half_rn((q2v*c + q1*sn) * qs);
        kd[i]    = __float2half_rn(k1*c - k2v*sn);
        kd[i+64] = __float2half_rn(k2v*c + k1*sn);
    }
}

// ---------------------------------------------------------------------------
// V transpose -> fp16 vt[bh][d][s]
// ---------------------------------------------------------------------------
__global__ __launch_bounds__(256) void vconv_kernel(
    const float* __restrict__ v, __half* __restrict__ vtg)
{
    __shared__ float t[32][33];
    int s0 = blockIdx.x * 32, d0 = blockIdx.y * 32, bh = blockIdx.z;
    int b = bh >> 4, h = bh & 15;
    int tx = threadIdx.x & 31, ty = threadIdx.x >> 5;
    #pragma unroll
    for (int i = 0; i < 4; i++)
        t[ty + 8*i][tx] = v[(size_t)(b*SEQ + s0 + ty + 8*i) * HID + h*HDIM + d0 + tx];
    __syncthreads();
    __half* vb = vtg + (size_t)bh * HDIM * SEQ;
    #pragma unroll
    for (int i = 0; i < 4; i++) {
        int d = d0 + ty + 8*i;
        vb[(size_t)d*SEQ + s0 + tx] = __float2half_rn(t[tx][ty + 8*i]);
    }
}

// ---------------------------------------------------------------------------
// HMMA flash attention, single-pass fp16 (proven in R7).
// ---------------------------------------------------------------------------
#define QS_STR 136
#define KS_STR 136
#define VS_STR 72
#define QS_OFF 0
#define KS_OFF (128*QS_STR)              // halves
#define KS_SZ  (64*KS_STR)
#define VS_OFF (KS_OFF + 2*KS_SZ)
#define VS_SZ  (128*VS_STR)
#define ATTN_SMEM ((VS_OFF + 2*VS_SZ)*2) // 106496 bytes

__global__ __launch_bounds__(256, 1) void attn_hmma_kernel(
    const __half* __restrict__ q2g, const __half* __restrict__ k2g,
    const __half* __restrict__ vtg, __half* __restrict__ ctxh)
{
    extern __shared__ char smraw[];
    uint32_t smb = smem_u32(smraw);
    int tid = threadIdx.x, wid = tid >> 5, lid = tid & 31;
    int qt = blockIdx.x, hh = blockIdx.y, b = blockIdx.z;
    int bh = b*NHEADS + hh;
    const __half* qbase = q2g + ((size_t)bh*SEQ + qt*128) * HDIM;
    const __half* kbase = k2g + (size_t)bh*SEQ * HDIM;
    const __half* vbase = vtg + (size_t)bh*HDIM*SEQ;

    #define LOAD_KT(st_, s0_) do {                                              \
        _Pragma("unroll")                                                       \
        for (int i_ = 0; i_ < 4; i_++) {                                        \
            int idx_ = tid + 256*i_; int row_ = idx_ >> 4, seg_ = idx_ & 15;    \
            cpasync16(smb + 2*(KS_OFF + (st_)*KS_SZ + row_*KS_STR + seg_*8),    \
                      kbase + ((size_t)((s0_) + row_))*HDIM + seg_*8);          \
        } } while (0)
    #define LOAD_VT(st_, s0_) do {                                              \
        _Pragma("unroll")                                                       \
        for (int i_ = 0; i_ < 4; i_++) {                                        \
            int idx_ = tid + 256*i_; int dr_ = idx_ >> 3, seg_ = idx_ & 7;      \
            cpasync16(smb + 2*(VS_OFF + (st_)*VS_SZ + dr_*VS_STR + seg_*8),     \
                      vbase + (size_t)dr_*SEQ + (s0_) + seg_*8);                \
        } } while (0)

    // prologue: Q tile + stage 0 in group0; stage 1 in group1
    #pragma unroll
    for (int i = 0; i < 8; i++) {
        int idx = tid + 256*i; int row = idx >> 4, seg = idx & 15;
        cpasync16(smb + 2*(QS_OFF + row*QS_STR + seg*8),
                  qbase + (size_t)row*HDIM + seg*8);
    }
    LOAD_KT(0, 0); LOAD_VT(0, 0);
    asm volatile("cp.async.commit_group;");
    LOAD_KT(1, 64); LOAD_VT(1, 64);
    asm volatile("cp.async.commit_group;");

    int g = lid >> 3, r = lid & 7;
    uint32_t aQ = smb + 2*(QS_OFF + (uint32_t)((wid*16 + r + (g&1)*8)*QS_STR + (g>>1)*8));
    uint32_t bK = smb + 2*(KS_OFF + (uint32_t)((r + (g>>1)*8)*KS_STR + (g&1)*8));
    uint32_t bV = smb + 2*(VS_OFF + (uint32_t)((r + (g>>1)*8)*VS_STR + (g&1)*8));

    float oacc[16][4];
    #pragma unroll
    for (int n = 0; n < 16; n++)
        #pragma unroll
        for (int e = 0; e < 4; e++) oacc[n][e] = 0.0f;
    float m0 = -INFINITY, m1 = -INFINITY, l0 = 0.0f, l1 = 0.0f;

    for (int it = 0; it < SEQ/64; it++) {
        asm volatile("cp.async.wait_group 1;");
        __syncthreads();
        uint32_t kst = (uint32_t)((it & 1) * KS_SZ) * 2;
        uint32_t vst = (uint32_t)((it & 1) * VS_SZ) * 2;

        // ---- scores: S[16q x 64s] = Q K^T
        float sacc[8][4];
        #pragma unroll
        for (int n = 0; n < 8; n++)
            #pragma unroll
            for (int e = 0; e < 4; e++) sacc[n][e] = 0.0f;

        #pragma unroll
        for (int ks = 0; ks < 8; ks++) {
            uint32_t bfr[8][2];
            #pragma unroll
            for (int np = 0; np < 4; np++) {
                uint32_t r0,r1,r2,r3;
                ldm_x4(r0,r1,r2,r3, bK + kst + 2*(uint32_t)(np*16*KS_STR + ks*16));
                bfr[np*2][0]=r0; bfr[np*2][1]=r1; bfr[np*2+1][0]=r2; bfr[np*2+1][1]=r3;
            }
            uint32_t a[4];
            ldm_x4(a[0],a[1],a[2],a[3], aQ + 2*(uint32_t)(ks*16));
            #pragma unroll
            for (int n = 0; n < 8; n++) mma16816h(sacc[n], a, bfr[n]);
        }

        // ---- online softmax (warp-local; rows lid>>2 and lid>>2 + 8)
        float mt0 = -INFINITY, mt1 = -INFINITY;
        #pragma unroll
        for (int n = 0; n < 8; n++) {
            mt0 = fmaxf(mt0, fmaxf(sacc[n][0], sacc[n][1]));
            mt1 = fmaxf(mt1, fmaxf(sacc[n][2], sacc[n][3]));
        }
        mt0 = fmaxf(mt0, __shfl_xor_sync(0xffffffffu, mt0, 1));
        mt0 = fmaxf(mt0, __shfl_xor_sync(0xffffffffu, mt0, 2));
        mt1 = fmaxf(mt1, __shfl_xor_sync(0xffffffffu, mt1, 1));
        mt1 = fmaxf(mt1, __shfl_xor_sync(0xffffffffu, mt1, 2));
        float mn0 = fmaxf(m0, mt0), mn1 = fmaxf(m1, mt1);
        float al0 = __expf(m0 - mn0), al1 = __expf(m1 - mn1);
        m0 = mn0; m1 = mn1;

        uint32_t ph0[8], ph1[8];
        float rs0 = 0.0f, rs1 = 0.0f;
        #pragma unroll
        for (int n = 0; n < 8; n++) {
            float p0 = __expf(sacc[n][0] - mn0);
            float p1 = __expf(sacc[n][1] - mn0);
            float p2 = __expf(sacc[n][2] - mn1);
            float p3 = __expf(sacc[n][3] - mn1);
            rs0 += p0 + p1; rs1 += p2 + p3;
            ph0[n] = packh(p0, p1);
            ph1[n] = packh(p2, p3);
        }
        rs0 += __shfl_xor_sync(0xffffffffu, rs0, 1);
        rs0 += __shfl_xor_sync(0xffffffffu, rs0, 2);
        rs1 += __shfl_xor_sync(0xffffffffu, rs1, 1);
        rs1 += __shfl_xor_sync(0xffffffffu, rs1, 2);
        l0 = l0*al0 + rs0; l1 = l1*al1 + rs1;
        #pragma unroll
        for (int n = 0; n < 16; n++) {
            oacc[n][0] *= al0; oacc[n][1] *= al0;
            oacc[n][2] *= al1; oacc[n][3] *= al1;
        }

        // ---- O += P V
        #pragma unroll
        for (int ks = 0; ks < 4; ks++) {
            uint32_t a[4] = { ph0[2*ks], ph1[2*ks], ph0[2*ks+1], ph1[2*ks+1] };
            #pragma unroll
            for (int np = 0; np < 8; np++) {
                uint32_t r0,r1,r2,r3;
                ldm_x4(r0,r1,r2,r3, bV + vst + 2*(uint32_t)(np*16*VS_STR + ks*16));
                uint32_t b0[2] = {r0, r1}, b1[2] = {r2, r3};
                mma16816h(oacc[np*2], a, b0); mma16816h(oacc[np*2+1], a, b1);
            }
        }

        __syncthreads();
        int itn = it + 2;
        if (itn < SEQ/64) {
            LOAD_KT(itn & 1, itn*64); LOAD_VT(itn & 1, itn*64);
        }
        asm volatile("cp.async.commit_group;");
    }

    // ---- epilogue: write fp16 ctx
    float inv0 = 1.0f / l0, inv1 = 1.0f / l1;
    int row0 = qt*128 + wid*16 + (lid >> 2);
    int colb = 2*(lid & 3);
    __half* cb = ctxh + ((size_t)(b*SEQ) + row0) * HID + hh*HDIM;
    #pragma unroll
    for (int n = 0; n < 16; n++) {
        *(__half2*)(cb + n*8 + colb) =
            __floats2half2_rn(oacc[n][0]*inv0, oacc[n][1]*inv0);
        *(__half2*)(cb + (size_t)8*HID + n*8 + colb) =
            __floats2half2_rn(oacc[n][2]*inv1, oacc[n][3]*inv1);
    }
    #undef LOAD_KT
    #undef LOAD_VT
}

// ---------------------------------------------------------------------------
// silu(g1)*g3 -> fp16 (2048 wide)
// ---------------------------------------------------------------------------
__global__ __launch_bounds__(256) void silu_h_kernel(
    const float* __restrict__ g1, const float* __restrict__ g3, __half* __restrict__ outh)
{
    int i = blockIdx.x * 256 + threadIdx.x;  // float4 index
    if (i >= MROWS * HID / 4) return;
    float4 a = ((const float4*)g1)[i];
    float4 b = ((const float4*)g3)[i];
    float vx = (a.x / (1.0f + expf(-a.x))) * b.x;
    float vy = (a.y / (1.0f + expf(-a.y))) * b.y;
    float vz = (a.z / (1.0f + expf(-a.z))) * b.z;
    float vw = (a.w / (1.0f + expf(-a.w))) * b.w;
    __half2* o = (__half2*)(outh + (size_t)i * 4);
    o[0] = __floats2half2_rn(vx, vy);
    o[1] = __floats2half2_rn(vz, vw);
}

// ---------------------------------------------------------------------------
// Launch
// ---------------------------------------------------------------------------
extern "C" void kernel_launch(void* const* d_in, const int* in_sizes, int n_in,
                              void* d_out, int out_size)
{
    (void)in_sizes; (void)n_in; (void)out_size;
    const float* hs  = (const float*)d_in[0];
    const float* Wq  = (const float*)d_in[1];
    const float* Wk  = (const float*)d_in[2];
    const float* Wv  = (const float*)d_in[3];
    const float* Wo  = (const float*)d_in[4];
    const float* w1  = (const float*)d_in[5];
    const float* w2  = (const float*)d_in[6];
    const float* w3  = (const float*)d_in[7];
    const float* ln1 = (const float*)d_in[8];
    const float* ln2 = (const float*)d_in[9];
    float* out = (float*)d_out;

    __half *xh, *ctxh, *g1h;
    __half *Wq2, *Wk2, *Wv2, *Wo2, *w12, *w22, *w32;
    __half *q2, *k2, *vt;
    float *q, *k, *v, *h, *g1, *g3;
    cudaGetSymbolAddress((void**)&xh,   g_xh);
    cudaGetSymbolAddress((void**)&ctxh, g_ctxh);
    cudaGetSymbolAddress((void**)&g1h,  g_g1h);
    cudaGetSymbolAddress((void**)&Wq2,  g_Wq2);
    cudaGetSymbolAddress((void**)&Wk2,  g_Wk2);
    cudaGetSymbolAddress((void**)&Wv2,  g_Wv2);
    cudaGetSymbolAddress((void**)&Wo2,  g_Wo2);
    cudaGetSymbolAddress((void**)&w12,  g_w12);
    cudaGetSymbolAddress((void**)&w22,  g_w22);
    cudaGetSymbolAddress((void**)&w32,  g_w32);
    cudaGetSymbolAddress((void**)&q2,   g_q2);
    cudaGetSymbolAddress((void**)&k2,   g_k2);
    cudaGetSymbolAddress((void**)&vt,   g_vt);
    cudaGetSymbolAddress((void**)&q,    g_q);
    cudaGetSymbolAddress((void**)&k,    g_k);
    cudaGetSymbolAddress((void**)&v,    g_v);
    cudaGetSymbolAddress((void**)&h,    g_h);
    cudaGetSymbolAddress((void**)&g1,   g_g1);
    cudaGetSymbolAddress((void**)&g3,   g_g3);

    cudaFuncSetAttribute(attn_hmma_kernel, cudaFuncAttributeMaxDynamicSharedMemorySize, ATTN_SMEM);
    cudaFuncSetAttribute(hmma_gemm_kernel, cudaFuncAttributeMaxDynamicSharedMemorySize, GEMM_SMEM);

    dim3 gemm_grid(MROWS / 128, HID / 128);      // (32, 16)
    dim3 wgrid(HID / 32, HID / 32);              // (64, 64)
    int nv4 = MROWS * HID / 4;

    rope_table_kernel<<<(SEQ * 64 + 255) / 256, 256>>>();

    wtrans_kernel<<<wgrid, 256>>>(Wq, Wq2);
    wtrans_kernel<<<wgrid, 256>>>(Wk, Wk2);
    wtrans_kernel<<<wgrid, 256>>>(Wv, Wv2);
    wtrans_kernel<<<wgrid, 256>>>(Wo, Wo2);
    wtrans_kernel<<<wgrid, 256>>>(w1, w12);
    wtrans_kernel<<<wgrid, 256>>>(w2, w22);
    wtrans_kernel<<<wgrid, 256>>>(w3, w32);

    rmsnorm_h_kernel<<<MROWS, 256>>>(hs, ln1, xh);

    hmma_gemm_kernel<<<gemm_grid, 256, GEMM_SMEM>>>(xh, Wq2, nullptr, q);
    hmma_gemm_kernel<<<gemm_grid, 256, GEMM_SMEM>>>(xh, Wk2, nullptr, k);
    hmma_gemm_kernel<<<gemm_grid, 256, GEMM_SMEM>>>(xh, Wv2, nullptr, v);

    rope_h_kernel<<<MROWS, 256>>>(q, k, q2, k2);
    vconv_kernel<<<dim3(SEQ/32, HDIM/32, BATCH*NHEADS), 256>>>(v, vt);

    attn_hmma_kernel<<<dim3(SEQ/128, NHEADS, BATCH), 256, ATTN_SMEM>>>(q2, k2, vt, ctxh);

    hmma_gemm_kernel<<<gemm_grid, 256, GEMM_SMEM>>>(ctxh, Wo2, hs, h);   // h = hs + ctx@Wo

    rmsnorm_h_kernel<<<MROWS, 256>>>(h, ln2, xh);                        // reuse xh as y

    hmma_gemm_kernel<<<gemm_grid, 256, GEMM_SMEM>>>(xh, w12, nullptr, g1);
    hmma_gemm_kernel<<<gemm_grid, 256, GEMM_SMEM>>>(xh, w32, nullptr, g3);

    silu_h_kernel<<<(nv4 + 255) / 256, 256>>>(g1, g3, g1h);

    hmma_gemm_kernel<<<gemm_grid, 256, GEMM_SMEM>>>(g1h, w22, h, out);   // out = h + mlp
}